// round 3
// baseline (speedup 1.0000x reference)
#include <cuda_runtime.h>
#include <math.h>

// Problem constants
#define B_   2
#define S_   2048
#define E_   2048
#define H_   16
#define HS_  128
#define M_   (B_ * S_)      // 4096
#define NQKV (3 * E_)       // 6144
#define KDIM E_             // 2048
#define ROT_ 32

// Scratch (device globals: no allocations allowed)
__device__ float g_Q[(size_t)B_ * H_ * S_ * HS_];
__device__ float g_K[(size_t)B_ * H_ * S_ * HS_];
__device__ float g_V[(size_t)B_ * H_ * S_ * HS_];
__device__ float g_Y[(size_t)B_ * S_ * E_];

// ---------------------------------------------------------------------------
// SGEMM: C[m,n] = sum_k A[m,k] * W[n,k] + bias[n]
// MODE 0: QKV — scatter epilogue into g_Q/g_K/g_V laid out [B,H,S,HS]
// MODE 1: dense — A is g_Y (read directly), write C
// 128x128 tile, BK=8, 256 threads, 8x8 microtile, double-buffered smem.
// ---------------------------------------------------------------------------
template <int MODE>
__global__ __launch_bounds__(256) void sgemm_kernel(
    const float* __restrict__ A, const float* __restrict__ W,
    const float* __restrict__ bias, float* __restrict__ C, int N)
{
    constexpr int BK = 8;
    __shared__ float As[2][BK][128];
    __shared__ float Bs[2][BK][128];

    const int tid  = threadIdx.x;
    const int tr   = tid >> 4;       // 0..15
    const int tc   = tid & 15;       // 0..15
    const int mBase = blockIdx.y * 128;
    const int nBase = blockIdx.x * 128;
    const int lrow = tid >> 1;       // 0..127
    const int lk   = (tid & 1) << 2; // 0 or 4

    const float* Aeff = (MODE == 1) ? g_Y : A;
    const float* Ap = Aeff + (size_t)(mBase + lrow) * KDIM + lk;
    const float* Wp = W    + (size_t)(nBase + lrow) * KDIM + lk;

    float acc[8][8];
    #pragma unroll
    for (int i = 0; i < 8; i++)
        #pragma unroll
        for (int j = 0; j < 8; j++) acc[i][j] = 0.f;

    // prologue: stage k-chunk 0 into buffer 0
    float4 av = *(const float4*)Ap;
    float4 bv = *(const float4*)Wp;
    As[0][lk+0][lrow] = av.x; As[0][lk+1][lrow] = av.y;
    As[0][lk+2][lrow] = av.z; As[0][lk+3][lrow] = av.w;
    Bs[0][lk+0][lrow] = bv.x; Bs[0][lk+1][lrow] = bv.y;
    Bs[0][lk+2][lrow] = bv.z; Bs[0][lk+3][lrow] = bv.w;
    __syncthreads();

    int buf = 0;
    for (int kb = BK; kb < KDIM; kb += BK) {
        // issue next chunk's global loads early
        av = *(const float4*)(Ap + kb);
        bv = *(const float4*)(Wp + kb);

        #pragma unroll
        for (int kk = 0; kk < BK; kk++) {
            float4 a0 = *(const float4*)&As[buf][kk][tr * 4];
            float4 a1 = *(const float4*)&As[buf][kk][64 + tr * 4];
            float4 b0 = *(const float4*)&Bs[buf][kk][tc * 4];
            float4 b1 = *(const float4*)&Bs[buf][kk][64 + tc * 4];
            float ar[8] = {a0.x, a0.y, a0.z, a0.w, a1.x, a1.y, a1.z, a1.w};
            float br[8] = {b0.x, b0.y, b0.z, b0.w, b1.x, b1.y, b1.z, b1.w};
            #pragma unroll
            for (int i = 0; i < 8; i++)
                #pragma unroll
                for (int j = 0; j < 8; j++)
                    acc[i][j] += ar[i] * br[j];
        }

        buf ^= 1;
        As[buf][lk+0][lrow] = av.x; As[buf][lk+1][lrow] = av.y;
        As[buf][lk+2][lrow] = av.z; As[buf][lk+3][lrow] = av.w;
        Bs[buf][lk+0][lrow] = bv.x; Bs[buf][lk+1][lrow] = bv.y;
        Bs[buf][lk+2][lrow] = bv.z; Bs[buf][lk+3][lrow] = bv.w;
        __syncthreads();
    }

    // final chunk
    #pragma unroll
    for (int kk = 0; kk < BK; kk++) {
        float4 a0 = *(const float4*)&As[buf][kk][tr * 4];
        float4 a1 = *(const float4*)&As[buf][kk][64 + tr * 4];
        float4 b0 = *(const float4*)&Bs[buf][kk][tc * 4];
        float4 b1 = *(const float4*)&Bs[buf][kk][64 + tc * 4];
        float ar[8] = {a0.x, a0.y, a0.z, a0.w, a1.x, a1.y, a1.z, a1.w};
        float br[8] = {b0.x, b0.y, b0.z, b0.w, b1.x, b1.y, b1.z, b1.w};
        #pragma unroll
        for (int i = 0; i < 8; i++)
            #pragma unroll
            for (int j = 0; j < 8; j++)
                acc[i][j] += ar[i] * br[j];
    }

    // epilogue: +bias, write as float4 groups (4 consecutive cols)
    #pragma unroll
    for (int ii = 0; ii < 8; ii++) {
        int m = mBase + ((ii < 4) ? (tr * 4 + ii) : (64 + tr * 4 + ii - 4));
        #pragma unroll
        for (int half = 0; half < 2; half++) {
            int nc = nBase + ((half == 0) ? (tc * 4) : (64 + tc * 4));
            float4 bb = *(const float4*)&bias[nc];
            float4 v;
            v.x = acc[ii][half * 4 + 0] + bb.x;
            v.y = acc[ii][half * 4 + 1] + bb.y;
            v.z = acc[ii][half * 4 + 2] + bb.z;
            v.w = acc[ii][half * 4 + 3] + bb.w;
            if (MODE == 0) {
                // n = h*384 + c ; c<128 -> Q, c<256 -> K, else V (tile-aligned)
                int h = nc / 384;
                int c = nc % 384;
                int b = m >> 11;
                int s = m & (S_ - 1);
                int base = ((b * H_ + h) * S_ + s) * HS_;
                float* dst;
                if (c < HS_)          dst = &g_Q[base + c];
                else if (c < 2 * HS_) dst = &g_K[base + c - HS_];
                else                  dst = &g_V[base + c - 2 * HS_];
                *(float4*)dst = v;
            } else {
                *(float4*)&C[(size_t)m * N + nc] = v;
            }
        }
    }
}

// ---------------------------------------------------------------------------
// RoPE: in-place rotate first ROT=32 dims of each (b,h,s) row of Q and K.
// Pair (j, j+16): new[j] = x[j]*cos - x[j+16]*sin ; new[j+16] = x[j+16]*cos + x[j]*sin
// angle = s * BASE^(-j/16)
// ---------------------------------------------------------------------------
__global__ __launch_bounds__(256) void rope_kernel()
{
    int idx = blockIdx.x * blockDim.x + threadIdx.x;
    if (idx >= B_ * H_ * S_ * (ROT_ / 2)) return;
    int j  = idx & 15;
    int s  = (idx >> 4) & (S_ - 1);
    int bh = idx >> 15;

    float inv = powf(10000.0f, -((float)j) / 16.0f);
    float ang = (float)s * inv;
    float c  = cosf(ang);
    float sn = sinf(ang);

    size_t base = ((size_t)bh * S_ + s) * HS_;
    float* q = &g_Q[base];
    float* k = &g_K[base];

    float q0 = q[j], q1 = q[j + 16];
    q[j]      = q0 * c - q1 * sn;
    q[j + 16] = q1 * c + q0 * sn;

    float k0 = k[j], k1 = k[j + 16];
    k[j]      = k0 * c - k1 * sn;
    k[j + 16] = k1 * c + k0 * sn;
}

// ---------------------------------------------------------------------------
// Flash attention (fp32, causal): per block one (b,h) x one 64-row Q tile.
// 256 threads = 16x16 grid; strided micro-tiles (rows ty+16i, cols tx+16j)
// for conflict-free smem reads. Q/K stored d-major [128][65] (transposed),
// V straight [64][128]; P staged through smem for the O GEMM.
// ---------------------------------------------------------------------------
#define FLASH_SMEM ((2 * 128 * 65 + 64 * 64) * 4)  // 82944 bytes

__global__ __launch_bounds__(256) void flash_kernel()
{
    extern __shared__ float sm[];
    float* Qs  = sm;                 // [128][65]  (Q^T, pre-scaled)
    float* KVs = sm + 128 * 65;      // K^T [128][65]  OR  V [64][128]
    float* Ps  = sm + 2 * 128 * 65;  // [64][64]

    const int tid = threadIdx.x;
    const int ty  = tid >> 4;   // 0..15
    const int tx  = tid & 15;   // 0..15
    const int bh  = blockIdx.y;                    // 0..31
    const int qt  = gridDim.x - 1 - blockIdx.x;    // big tiles first
    const int qBase = qt * 64;

    const float* Qg = g_Q + ((size_t)bh * S_ + qBase) * HS_;
    const float* Kg = g_K + (size_t)bh * S_ * HS_;
    const float* Vg = g_V + (size_t)bh * S_ * HS_;
    const float scale = 0.08838834764831845f;  // 1/sqrt(128)

    // load Q tile transposed + pre-scaled
    #pragma unroll
    for (int it = 0; it < 8; it++) {
        int f4 = it * 256 + tid;
        int r  = f4 >> 5;
        int d0 = (f4 & 31) << 2;
        float4 v = *(const float4*)(Qg + r * HS_ + d0);
        Qs[(d0 + 0) * 65 + r] = v.x * scale;
        Qs[(d0 + 1) * 65 + r] = v.y * scale;
        Qs[(d0 + 2) * 65 + r] = v.z * scale;
        Qs[(d0 + 3) * 65 + r] = v.w * scale;
    }

    float m_i[4], l_i[4], acc[4][8];
    #pragma unroll
    for (int i = 0; i < 4; i++) {
        m_i[i] = -1e30f;
        l_i[i] = 0.f;
        #pragma unroll
        for (int j = 0; j < 8; j++) acc[i][j] = 0.f;
    }

    for (int t = 0; t <= qt; t++) {
        // --- load K tile transposed ---
        const float* Kt = Kg + (size_t)t * 64 * HS_;
        #pragma unroll
        for (int it = 0; it < 8; it++) {
            int f4 = it * 256 + tid;
            int r  = f4 >> 5;
            int d0 = (f4 & 31) << 2;
            float4 v = *(const float4*)(Kt + r * HS_ + d0);
            KVs[(d0 + 0) * 65 + r] = v.x;
            KVs[(d0 + 1) * 65 + r] = v.y;
            KVs[(d0 + 2) * 65 + r] = v.z;
            KVs[(d0 + 3) * 65 + r] = v.w;
        }
        __syncthreads();

        // --- S = Q K^T (scaled) ---
        float s[4][4];
        #pragma unroll
        for (int i = 0; i < 4; i++)
            #pragma unroll
            for (int j = 0; j < 4; j++) s[i][j] = 0.f;

        #pragma unroll 8
        for (int d = 0; d < 128; d++) {
            float q0 = Qs[d * 65 + ty];
            float q1 = Qs[d * 65 + ty + 16];
            float q2 = Qs[d * 65 + ty + 32];
            float q3 = Qs[d * 65 + ty + 48];
            float k0 = KVs[d * 65 + tx];
            float k1 = KVs[d * 65 + tx + 16];
            float k2 = KVs[d * 65 + tx + 32];
            float k3 = KVs[d * 65 + tx + 48];
            s[0][0] += q0 * k0; s[0][1] += q0 * k1; s[0][2] += q0 * k2; s[0][3] += q0 * k3;
            s[1][0] += q1 * k0; s[1][1] += q1 * k1; s[1][2] += q1 * k2; s[1][3] += q1 * k3;
            s[2][0] += q2 * k0; s[2][1] += q2 * k1; s[2][2] += q2 * k2; s[2][3] += q2 * k3;
            s[3][0] += q3 * k0; s[3][1] += q3 * k1; s[3][2] += q3 * k2; s[3][3] += q3 * k3;
        }
        __syncthreads();  // done reading K; KVs can be reused for V

        // --- load V tile (straight) while doing register-only softmax ---
        const float* Vt = Vg + (size_t)t * 64 * HS_;
        #pragma unroll
        for (int it = 0; it < 8; it++) {
            int f4 = it * 256 + tid;
            int r  = f4 >> 5;
            int d0 = (f4 & 31) << 2;
            *(float4*)(KVs + r * 128 + d0) = *(const float4*)(Vt + r * HS_ + d0);
        }

        // causal mask only on the diagonal tile (tiles are aligned 64x64)
        if (t == qt) {
            #pragma unroll
            for (int i = 0; i < 4; i++)
                #pragma unroll
                for (int j = 0; j < 4; j++)
                    if (tx + 16 * j > ty + 16 * i) s[i][j] = -1e30f;
        }

        // --- online softmax (row stats reduced over the 16 tx lanes) ---
        #pragma unroll
        for (int i = 0; i < 4; i++) {
            float mt = fmaxf(fmaxf(s[i][0], s[i][1]), fmaxf(s[i][2], s[i][3]));
            mt = fmaxf(mt, __shfl_xor_sync(0xffffffffu, mt, 1));
            mt = fmaxf(mt, __shfl_xor_sync(0xffffffffu, mt, 2));
            mt = fmaxf(mt, __shfl_xor_sync(0xffffffffu, mt, 4));
            mt = fmaxf(mt, __shfl_xor_sync(0xffffffffu, mt, 8));
            float mnew  = fmaxf(m_i[i], mt);
            float alpha = expf(m_i[i] - mnew);
            float rs = 0.f;
            #pragma unroll
            for (int j = 0; j < 4; j++) {
                float p = expf(s[i][j] - mnew);
                s[i][j] = p;
                rs += p;
            }
            rs += __shfl_xor_sync(0xffffffffu, rs, 1);
            rs += __shfl_xor_sync(0xffffffffu, rs, 2);
            rs += __shfl_xor_sync(0xffffffffu, rs, 4);
            rs += __shfl_xor_sync(0xffffffffu, rs, 8);
            l_i[i] = l_i[i] * alpha + rs;
            m_i[i] = mnew;
            #pragma unroll
            for (int j = 0; j < 8; j++) acc[i][j] *= alpha;
            #pragma unroll
            for (int j = 0; j < 4; j++)
                Ps[(ty + 16 * i) * 64 + tx + 16 * j] = s[i][j];
        }
        __syncthreads();  // P + V visible

        // --- O += P V ---
        #pragma unroll 4
        for (int c = 0; c < 64; c++) {
            float p0 = Ps[(ty     ) * 64 + c];
            float p1 = Ps[(ty + 16) * 64 + c];
            float p2 = Ps[(ty + 32) * 64 + c];
            float p3 = Ps[(ty + 48) * 64 + c];
            #pragma unroll
            for (int j = 0; j < 8; j++) {
                float vv = KVs[c * 128 + tx + 16 * j];
                acc[0][j] += p0 * vv;
                acc[1][j] += p1 * vv;
                acc[2][j] += p2 * vv;
                acc[3][j] += p3 * vv;
            }
        }
        __syncthreads();  // done with V before next K overwrite
    }

    // --- normalize + write to g_Y laid out [B, S, E] ---
    int b = bh >> 4, h = bh & 15;
    #pragma unroll
    for (int i = 0; i < 4; i++) {
        int r = qBase + ty + 16 * i;
        float inv = 1.f / l_i[i];
        float* Yp = g_Y + ((size_t)b * S_ + r) * E_ + h * HS_;
        #pragma unroll
        for (int j = 0; j < 8; j++)
            Yp[tx + 16 * j] = acc[i][j] * inv;
    }
}

// ---------------------------------------------------------------------------
// Launch
// ---------------------------------------------------------------------------
extern "C" void kernel_launch(void* const* d_in, const int* in_sizes, int n_in,
                              void* d_out, int out_size)
{
    const float* x       = (const float*)d_in[0];
    const float* w_qkv   = (const float*)d_in[1];
    const float* b_qkv   = (const float*)d_in[2];
    const float* w_dense = (const float*)d_in[3];
    const float* b_dense = (const float*)d_in[4];
    float* out = (float*)d_out;

    // 1. QKV projection + bias, scattered into [B,H,S,HS] Q/K/V
    sgemm_kernel<0><<<dim3(NQKV / 128, M_ / 128), 256>>>(x, w_qkv, b_qkv, nullptr, NQKV);

    // 2. RoPE on first 32 dims of Q and K
    rope_kernel<<<(B_ * H_ * S_ * (ROT_ / 2)) / 256, 256>>>();

    // 3. Causal flash attention -> g_Y [B,S,E]
    cudaFuncSetAttribute(flash_kernel, cudaFuncAttributeMaxDynamicSharedMemorySize, FLASH_SMEM);
    flash_kernel<<<dim3(S_ / 64, B_ * H_), 256, FLASH_SMEM>>>();

    // 4. Dense projection + bias -> output
    sgemm_kernel<1><<<dim3(E_ / 128, M_ / 128), 256>>>(nullptr, w_dense, b_dense, out, E_);
}

// round 7
// speedup vs baseline: 1.7760x; 1.7760x over previous
#include <cuda_runtime.h>
#include <math.h>
#include <stdint.h>

// Problem constants
#define B_   2
#define S_   2048
#define E_   2048
#define H_   16
#define HS_  128
#define M_   (B_ * S_)      // 4096
#define NQKV (3 * E_)       // 6144
#define KDIM E_             // 2048
#define ROT_ 32

// Scratch (device globals: no allocations allowed)
__device__ float g_Q[(size_t)B_ * H_ * S_ * HS_];
__device__ float g_K[(size_t)B_ * H_ * S_ * HS_];
__device__ float g_V[(size_t)B_ * H_ * S_ * HS_];
__device__ float g_Y[(size_t)B_ * S_ * E_];     // flash output, tf32-rounded
__device__ float g_Xr[(size_t)M_ * E_];         // x rounded to tf32
__device__ float g_Wqr[(size_t)NQKV * E_];      // w_qkv rounded to tf32
__device__ float g_Wdr[(size_t)E_ * E_];        // w_dense rounded to tf32

// ---------------------------------------------------------------------------
// Helpers
// ---------------------------------------------------------------------------
__device__ __forceinline__ uint32_t smem_to_u32(const void* p) {
    uint32_t a;
    asm("{ .reg .u64 t; cvta.to.shared.u64 t, %1; cvt.u32.u64 %0, t; }"
        : "=r"(a) : "l"(p));
    return a;
}

__device__ __forceinline__ void cp_async16(uint32_t dst, const void* src) {
    asm volatile("cp.async.cg.shared.global [%0], [%1], 16;" :: "r"(dst), "l"(src));
}
#define CP_COMMIT() asm volatile("cp.async.commit_group;" ::: "memory")
template <int N>
__device__ __forceinline__ void cp_wait() {
    asm volatile("cp.async.wait_group %0;" :: "n"(N) : "memory");
}

__device__ __forceinline__ float round_tf32(float x) {
    uint32_t b;
    asm("cvt.rna.tf32.f32 %0, %1;" : "=r"(b) : "f"(x));
    return __uint_as_float(b);
}

// mma.sync m16n8k8 tf32: D = A(16x8,row) * B(8x8,col) + D
__device__ __forceinline__ void mma_tf32(float* d, const uint32_t* a, const uint32_t* b) {
    asm volatile(
        "mma.sync.aligned.m16n8k8.row.col.f32.tf32.tf32.f32 "
        "{%0,%1,%2,%3}, {%4,%5,%6,%7}, {%8,%9}, {%0,%1,%2,%3};"
        : "+f"(d[0]), "+f"(d[1]), "+f"(d[2]), "+f"(d[3])
        : "r"(a[0]), "r"(a[1]), "r"(a[2]), "r"(a[3]), "r"(b[0]), "r"(b[1]));
}

// ---------------------------------------------------------------------------
// Round fp32 -> tf32 (RN) into device-global copies
// which: 0 -> g_Xr, 1 -> g_Wqr, 2 -> g_Wdr
// ---------------------------------------------------------------------------
__global__ __launch_bounds__(256) void round_kernel(const float* __restrict__ src,
                                                    int which, int n4)
{
    float* dst = (which == 0) ? g_Xr : (which == 1) ? g_Wqr : g_Wdr;
    int i = blockIdx.x * blockDim.x + threadIdx.x;
    if (i >= n4) return;
    float4 v = ((const float4*)src)[i];
    v.x = round_tf32(v.x); v.y = round_tf32(v.y);
    v.z = round_tf32(v.z); v.w = round_tf32(v.w);
    ((float4*)dst)[i] = v;
}

// ---------------------------------------------------------------------------
// mma.sync tf32 GEMM: C[m,n] = sum_k A[m,k] * W[n,k] + bias[n]
// MODE 0: A=g_Xr, W=g_Wqr, scatter epilogue into g_Q/g_K/g_V [B,H,S,HS]
// MODE 1: A=g_Y,  W=g_Wdr, write C
// CTA tile 128x128, BK=32, 8 warps (2m x 4n), warp tile 64x32 (4x4 of m16n8k8).
// Smem rows padded to 36 floats: frag lds.32 banks = (g*4+q)%32, conflict-free.
// ---------------------------------------------------------------------------
#define GROW 36                       // floats per smem row (32 + 4 pad)
#define STG_F (128 * GROW)            // floats per stage per operand (4608)
#define GEMM_SMEM (4 * STG_F * 4)     // 2 bufs * 2 operands = 73728 bytes

__device__ __forceinline__ void scatter_qkv2(int m, int n, float v0, float v1) {
    int b = m >> 11;
    int srow = m & (S_ - 1);
    int h = n / 384;
    int c = n % 384;
    size_t base = ((size_t)(b * H_ + h) * S_ + srow) * HS_;
    float* dst = (c < HS_) ? g_Q + base + c
               : (c < 2 * HS_) ? g_K + base + (c - HS_)
               : g_V + base + (c - 2 * HS_);
    *(float2*)dst = make_float2(v0, v1);
}

template <int MODE>
__global__ __launch_bounds__(256) void mma_gemm(
    const float* __restrict__ bias, float* __restrict__ C)
{
    extern __shared__ float smf[];
    float* As = smf;                  // [2][128][GROW]
    float* Bs = smf + 2 * STG_F;      // [2][128][GROW]
    const uint32_t aAddr = smem_to_u32(As);
    const uint32_t bAddr = smem_to_u32(Bs);

    const int tid  = threadIdx.x;
    const int wid  = tid >> 5;
    const int lane = tid & 31;
    const int g    = lane >> 2;       // 0..7
    const int q    = lane & 3;        // 0..3
    const int wm   = wid & 1;         // 2 m-warps
    const int wn   = wid >> 1;        // 4 n-warps
    const int mBase = blockIdx.y * 128;
    const int nBase = blockIdx.x * 128;

    const float* Ag = (MODE == 0) ? g_Xr : g_Y;
    const float* Wg = (MODE == 0) ? g_Wqr : g_Wdr;

    float d[4][4][4];
    #pragma unroll
    for (int mt = 0; mt < 4; mt++)
        #pragma unroll
        for (int nt = 0; nt < 4; nt++)
            #pragma unroll
            for (int r = 0; r < 4; r++) d[mt][nt][r] = 0.f;

    // stage loader: 4 float4 of A + 4 float4 of B per thread
    auto load_stage = [&](int km, int buf) {
        uint32_t ad = aAddr + buf * (STG_F * 4);
        uint32_t bd = bAddr + buf * (STG_F * 4);
        const float* ap = Ag + (size_t)mBase * KDIM + km * 32;
        const float* wp = Wg + (size_t)nBase * KDIM + km * 32;
        #pragma unroll
        for (int t = 0; t < 4; t++) {
            int f4 = t * 256 + tid;
            int r = f4 >> 3, c = f4 & 7;
            cp_async16(ad + r * (GROW * 4) + c * 16, ap + (size_t)r * KDIM + c * 4);
            cp_async16(bd + r * (GROW * 4) + c * 16, wp + (size_t)r * KDIM + c * 4);
        }
        CP_COMMIT();
    };

    load_stage(0, 0);

    for (int km = 0; km < KDIM / 32; km++) {
        int buf = km & 1;
        if (km + 1 < KDIM / 32) {
            load_stage(km + 1, buf ^ 1);
            cp_wait<1>();          // stage km complete
        } else {
            cp_wait<0>();
        }
        __syncthreads();           // stage km visible to all warps

        const float* Ab = As + buf * STG_F + (wm * 64) * GROW;
        const float* Bb = Bs + buf * STG_F + (wn * 32) * GROW;
        #pragma unroll
        for (int kk = 0; kk < 4; kk++) {
            int kc = kk * 8 + q;
            uint32_t a[4][4], b[4][2];
            #pragma unroll
            for (int mt = 0; mt < 4; mt++) {
                const float* p = Ab + (mt * 16 + g) * GROW + kc;
                a[mt][0] = __float_as_uint(p[0]);            // (g,     q)
                a[mt][1] = __float_as_uint(p[8 * GROW]);     // (g+8,   q)
                a[mt][2] = __float_as_uint(p[4]);            // (g,     q+4)
                a[mt][3] = __float_as_uint(p[8 * GROW + 4]); // (g+8,   q+4)
            }
            #pragma unroll
            for (int nt = 0; nt < 4; nt++) {
                const float* p = Bb + (nt * 8 + g) * GROW + kc;
                b[nt][0] = __float_as_uint(p[0]);            // (q,   g)
                b[nt][1] = __float_as_uint(p[4]);            // (q+4, g)
            }
            #pragma unroll
            for (int mt = 0; mt < 4; mt++)
                #pragma unroll
                for (int nt = 0; nt < 4; nt++)
                    mma_tf32(d[mt][nt], a[mt], b[nt]);
        }
        __syncthreads();           // all warps done with buf before overwrite
    }

    // epilogue: c0=(g,2q), c1=(g,2q+1), c2=(g+8,2q), c3=(g+8,2q+1)
    #pragma unroll
    for (int mt = 0; mt < 4; mt++) {
        int m0 = mBase + wm * 64 + mt * 16 + g;
        #pragma unroll
        for (int nt = 0; nt < 4; nt++) {
            int n0 = nBase + wn * 32 + nt * 8 + 2 * q;
            float2 bb = *(const float2*)&bias[n0];
            float v0 = d[mt][nt][0] + bb.x;
            float v1 = d[mt][nt][1] + bb.y;
            float v2 = d[mt][nt][2] + bb.x;
            float v3 = d[mt][nt][3] + bb.y;
            if (MODE == 0) {
                scatter_qkv2(m0,     n0, v0, v1);
                scatter_qkv2(m0 + 8, n0, v2, v3);
            } else {
                *(float2*)&C[(size_t)m0 * E_ + n0]       = make_float2(v0, v1);
                *(float2*)&C[(size_t)(m0 + 8) * E_ + n0] = make_float2(v2, v3);
            }
        }
    }
}

// ---------------------------------------------------------------------------
// RoPE: rotate first ROT=32 dims of each (b,h,s) row of Q and K.
// ---------------------------------------------------------------------------
__global__ __launch_bounds__(256) void rope_kernel()
{
    int idx = blockIdx.x * blockDim.x + threadIdx.x;
    if (idx >= B_ * H_ * S_ * (ROT_ / 2)) return;
    int j  = idx & 15;
    int s  = (idx >> 4) & (S_ - 1);
    int bh = idx >> 15;

    float inv = powf(10000.0f, -((float)j) / 16.0f);
    float ang = (float)s * inv;
    float c  = cosf(ang);
    float sn = sinf(ang);

    size_t base = ((size_t)bh * S_ + s) * HS_;
    float* qp = &g_Q[base];
    float* kp = &g_K[base];

    float q0 = qp[j], q1 = qp[j + 16];
    qp[j]      = q0 * c - q1 * sn;
    qp[j + 16] = q1 * c + q0 * sn;

    float k0 = kp[j], k1 = kp[j + 16];
    kp[j]      = k0 * c - k1 * sn;
    kp[j + 16] = k1 * c + k0 * sn;
}

// ---------------------------------------------------------------------------
// Flash attention (fp32, causal) — __expf; tf32-rounded output
// ---------------------------------------------------------------------------
#define FLASH_SMEM ((2 * 128 * 65 + 64 * 64) * 4)  // 82944 bytes

__global__ __launch_bounds__(256) void flash_kernel()
{
    extern __shared__ float sm[];
    float* Qs  = sm;                 // [128][65]  (Q^T, pre-scaled)
    float* KVs = sm + 128 * 65;      // K^T [128][65]  OR  V [64][128]
    float* Ps  = sm + 2 * 128 * 65;  // [64][64]

    const int tid = threadIdx.x;
    const int ty  = tid >> 4;
    const int tx  = tid & 15;
    const int bh  = blockIdx.y;
    const int qt  = gridDim.x - 1 - blockIdx.x;
    const int qBase = qt * 64;

    const float* Qg = g_Q + ((size_t)bh * S_ + qBase) * HS_;
    const float* Kg = g_K + (size_t)bh * S_ * HS_;
    const float* Vg = g_V + (size_t)bh * S_ * HS_;
    const float scale = 0.08838834764831845f;

    #pragma unroll
    for (int it = 0; it < 8; it++) {
        int f4 = it * 256 + tid;
        int r  = f4 >> 5;
        int d0 = (f4 & 31) << 2;
        float4 v = *(const float4*)(Qg + r * HS_ + d0);
        Qs[(d0 + 0) * 65 + r] = v.x * scale;
        Qs[(d0 + 1) * 65 + r] = v.y * scale;
        Qs[(d0 + 2) * 65 + r] = v.z * scale;
        Qs[(d0 + 3) * 65 + r] = v.w * scale;
    }

    float m_i[4], l_i[4], acc[4][8];
    #pragma unroll
    for (int i = 0; i < 4; i++) {
        m_i[i] = -1e30f;
        l_i[i] = 0.f;
        #pragma unroll
        for (int j = 0; j < 8; j++) acc[i][j] = 0.f;
    }

    for (int t = 0; t <= qt; t++) {
        const float* Kt = Kg + (size_t)t * 64 * HS_;
        #pragma unroll
        for (int it = 0; it < 8; it++) {
            int f4 = it * 256 + tid;
            int r  = f4 >> 5;
            int d0 = (f4 & 31) << 2;
            float4 v = *(const float4*)(Kt + r * HS_ + d0);
            KVs[(d0 + 0) * 65 + r] = v.x;
            KVs[(d0 + 1) * 65 + r] = v.y;
            KVs[(d0 + 2) * 65 + r] = v.z;
            KVs[(d0 + 3) * 65 + r] = v.w;
        }
        __syncthreads();

        float s[4][4];
        #pragma unroll
        for (int i = 0; i < 4; i++)
            #pragma unroll
            for (int j = 0; j < 4; j++) s[i][j] = 0.f;

        #pragma unroll 8
        for (int d = 0; d < 128; d++) {
            float q0 = Qs[d * 65 + ty];
            float q1 = Qs[d * 65 + ty + 16];
            float q2 = Qs[d * 65 + ty + 32];
            float q3 = Qs[d * 65 + ty + 48];
            float k0 = KVs[d * 65 + tx];
            float k1 = KVs[d * 65 + tx + 16];
            float k2 = KVs[d * 65 + tx + 32];
            float k3 = KVs[d * 65 + tx + 48];
            s[0][0] += q0 * k0; s[0][1] += q0 * k1; s[0][2] += q0 * k2; s[0][3] += q0 * k3;
            s[1][0] += q1 * k0; s[1][1] += q1 * k1; s[1][2] += q1 * k2; s[1][3] += q1 * k3;
            s[2][0] += q2 * k0; s[2][1] += q2 * k1; s[2][2] += q2 * k2; s[2][3] += q2 * k3;
            s[3][0] += q3 * k0; s[3][1] += q3 * k1; s[3][2] += q3 * k2; s[3][3] += q3 * k3;
        }
        __syncthreads();

        const float* Vt = Vg + (size_t)t * 64 * HS_;
        #pragma unroll
        for (int it = 0; it < 8; it++) {
            int f4 = it * 256 + tid;
            int r  = f4 >> 5;
            int d0 = (f4 & 31) << 2;
            *(float4*)(KVs + r * 128 + d0) = *(const float4*)(Vt + r * HS_ + d0);
        }

        if (t == qt) {
            #pragma unroll
            for (int i = 0; i < 4; i++)
                #pragma unroll
                for (int j = 0; j < 4; j++)
                    if (tx + 16 * j > ty + 16 * i) s[i][j] = -1e30f;
        }

        #pragma unroll
        for (int i = 0; i < 4; i++) {
            float mt = fmaxf(fmaxf(s[i][0], s[i][1]), fmaxf(s[i][2], s[i][3]));
            mt = fmaxf(mt, __shfl_xor_sync(0xffffffffu, mt, 1));
            mt = fmaxf(mt, __shfl_xor_sync(0xffffffffu, mt, 2));
            mt = fmaxf(mt, __shfl_xor_sync(0xffffffffu, mt, 4));
            mt = fmaxf(mt, __shfl_xor_sync(0xffffffffu, mt, 8));
            float mnew  = fmaxf(m_i[i], mt);
            float alpha = __expf(m_i[i] - mnew);
            float rs = 0.f;
            #pragma unroll
            for (int j = 0; j < 4; j++) {
                float p = __expf(s[i][j] - mnew);
                s[i][j] = p;
                rs += p;
            }
            rs += __shfl_xor_sync(0xffffffffu, rs, 1);
            rs += __shfl_xor_sync(0xffffffffu, rs, 2);
            rs += __shfl_xor_sync(0xffffffffu, rs, 4);
            rs += __shfl_xor_sync(0xffffffffu, rs, 8);
            l_i[i] = l_i[i] * alpha + rs;
            m_i[i] = mnew;
            #pragma unroll
            for (int j = 0; j < 8; j++) acc[i][j] *= alpha;
            #pragma unroll
            for (int j = 0; j < 4; j++)
                Ps[(ty + 16 * i) * 64 + tx + 16 * j] = s[i][j];
        }
        __syncthreads();

        #pragma unroll 4
        for (int c = 0; c < 64; c++) {
            float p0 = Ps[(ty     ) * 64 + c];
            float p1 = Ps[(ty + 16) * 64 + c];
            float p2 = Ps[(ty + 32) * 64 + c];
            float p3 = Ps[(ty + 48) * 64 + c];
            #pragma unroll
            for (int j = 0; j < 8; j++) {
                float vv = KVs[c * 128 + tx + 16 * j];
                acc[0][j] += p0 * vv;
                acc[1][j] += p1 * vv;
                acc[2][j] += p2 * vv;
                acc[3][j] += p3 * vv;
            }
        }
        __syncthreads();
    }

    // normalize + tf32-round + write to g_Y [B, S, E] (dense GEMM input)
    int b = bh >> 4, h = bh & 15;
    #pragma unroll
    for (int i = 0; i < 4; i++) {
        int r = qBase + ty + 16 * i;
        float inv = 1.f / l_i[i];
        float* Yp = g_Y + ((size_t)b * S_ + r) * E_ + h * HS_;
        #pragma unroll
        for (int j = 0; j < 8; j++)
            Yp[tx + 16 * j] = round_tf32(acc[i][j] * inv);
    }
}

// ---------------------------------------------------------------------------
// Launch
// ---------------------------------------------------------------------------
extern "C" void kernel_launch(void* const* d_in, const int* in_sizes, int n_in,
                              void* d_out, int out_size)
{
    const float* x       = (const float*)d_in[0];
    const float* w_qkv   = (const float*)d_in[1];
    const float* b_qkv   = (const float*)d_in[2];
    const float* w_dense = (const float*)d_in[3];
    const float* b_dense = (const float*)d_in[4];
    float* out = (float*)d_out;

    cudaFuncSetAttribute(mma_gemm<0>, cudaFuncAttributeMaxDynamicSharedMemorySize, GEMM_SMEM);
    cudaFuncSetAttribute(mma_gemm<1>, cudaFuncAttributeMaxDynamicSharedMemorySize, GEMM_SMEM);
    cudaFuncSetAttribute(flash_kernel, cudaFuncAttributeMaxDynamicSharedMemorySize, FLASH_SMEM);

    // 0. Round GEMM inputs to tf32 (RN) — removes truncation bias
    round_kernel<<<(M_ * E_ / 4 + 255) / 256, 256>>>(x, 0, M_ * E_ / 4);
    round_kernel<<<(NQKV * E_ / 4 + 255) / 256, 256>>>(w_qkv, 1, NQKV * E_ / 4);
    round_kernel<<<(E_ * E_ / 4 + 255) / 256, 256>>>(w_dense, 2, E_ * E_ / 4);

    // 1. QKV projection (mma.sync tf32) + bias, scattered into [B,H,S,HS]
    mma_gemm<0><<<dim3(NQKV / 128, M_ / 128), 256, GEMM_SMEM>>>(b_qkv, nullptr);

    // 2. RoPE on first 32 dims of Q and K
    rope_kernel<<<(B_ * H_ * S_ * (ROT_ / 2)) / 256, 256>>>();

    // 3. Causal flash attention -> g_Y (tf32-rounded)
    flash_kernel<<<dim3(S_ / 64, B_ * H_), 256, FLASH_SMEM>>>();

    // 4. Dense projection (mma.sync tf32) + bias -> output
    mma_gemm<1><<<dim3(E_ / 128, M_ / 128), 256, GEMM_SMEM>>>(b_dense, out);
}

// round 9
// speedup vs baseline: 3.1240x; 1.7590x over previous
#include <cuda_runtime.h>
#include <math.h>
#include <stdint.h>

// Problem constants
#define B_   2
#define S_   2048
#define E_   2048
#define H_   16
#define HS_  128
#define M_   (B_ * S_)      // 4096
#define NQKV (3 * E_)       // 6144
#define KDIM E_             // 2048
#define ROT_ 32
#define QSCALE 0.08838834764831845f   // 1/sqrt(128)

// Scratch (device globals: no allocations allowed)
__device__ float g_Q[(size_t)B_ * H_ * S_ * HS_];   // pre-scaled by QSCALE, tf32-rounded
__device__ float g_K[(size_t)B_ * H_ * S_ * HS_];   // tf32-rounded
__device__ float g_V[(size_t)B_ * H_ * S_ * HS_];   // tf32-rounded
__device__ float g_Y[(size_t)B_ * S_ * E_];         // flash output, tf32-rounded
__device__ float g_Xr[(size_t)M_ * E_];             // x rounded to tf32
__device__ float g_Wqr[(size_t)NQKV * E_];          // w_qkv rounded to tf32
__device__ float g_Wdr[(size_t)E_ * E_];            // w_dense rounded to tf32

// ---------------------------------------------------------------------------
// Helpers
// ---------------------------------------------------------------------------
__device__ __forceinline__ uint32_t smem_to_u32(const void* p) {
    uint32_t a;
    asm("{ .reg .u64 t; cvta.to.shared.u64 t, %1; cvt.u32.u64 %0, t; }"
        : "=r"(a) : "l"(p));
    return a;
}

__device__ __forceinline__ void cp_async16(uint32_t dst, const void* src) {
    asm volatile("cp.async.cg.shared.global [%0], [%1], 16;" :: "r"(dst), "l"(src));
}
#define CP_COMMIT() asm volatile("cp.async.commit_group;" ::: "memory")
template <int N>
__device__ __forceinline__ void cp_wait() {
    asm volatile("cp.async.wait_group %0;" :: "n"(N) : "memory");
}

__device__ __forceinline__ float round_tf32(float x) {
    uint32_t b;
    asm("cvt.rna.tf32.f32 %0, %1;" : "=r"(b) : "f"(x));
    return __uint_as_float(b);
}

// mma.sync m16n8k8 tf32: D = A(16x8,row) * B(8x8,col) + D
__device__ __forceinline__ void mma_tf32(float* d, const uint32_t* a, const uint32_t* b) {
    asm volatile(
        "mma.sync.aligned.m16n8k8.row.col.f32.tf32.tf32.f32 "
        "{%0,%1,%2,%3}, {%4,%5,%6,%7}, {%8,%9}, {%0,%1,%2,%3};"
        : "+f"(d[0]), "+f"(d[1]), "+f"(d[2]), "+f"(d[3])
        : "r"(a[0]), "r"(a[1]), "r"(a[2]), "r"(a[3]), "r"(b[0]), "r"(b[1]));
}

// ---------------------------------------------------------------------------
// Round fp32 -> tf32 (RN) into device-global copies
// ---------------------------------------------------------------------------
__global__ __launch_bounds__(256) void round_kernel(const float* __restrict__ src,
                                                    int which, int n4)
{
    float* dst = (which == 0) ? g_Xr : (which == 1) ? g_Wqr : g_Wdr;
    int i = blockIdx.x * blockDim.x + threadIdx.x;
    if (i >= n4) return;
    float4 v = ((const float4*)src)[i];
    v.x = round_tf32(v.x); v.y = round_tf32(v.y);
    v.z = round_tf32(v.z); v.w = round_tf32(v.w);
    ((float4*)dst)[i] = v;
}

// ---------------------------------------------------------------------------
// mma.sync tf32 GEMM (unchanged structure; MODE 0 epilogue now rounds Q/K/V
// to tf32 and pre-scales Q by QSCALE)
// ---------------------------------------------------------------------------
#define GROW 36
#define STG_F (128 * GROW)
#define GEMM_SMEM (4 * STG_F * 4)     // 73728 bytes

__device__ __forceinline__ void scatter_qkv2(int m, int n, float v0, float v1) {
    int b = m >> 11;
    int srow = m & (S_ - 1);
    int h = n / 384;
    int c = n % 384;
    size_t base = ((size_t)(b * H_ + h) * S_ + srow) * HS_;
    float* dst;
    if (c < HS_) {
        dst = g_Q + base + c;
        v0 *= QSCALE; v1 *= QSCALE;
    } else if (c < 2 * HS_) {
        dst = g_K + base + (c - HS_);
    } else {
        dst = g_V + base + (c - 2 * HS_);
    }
    *(float2*)dst = make_float2(round_tf32(v0), round_tf32(v1));
}

template <int MODE>
__global__ __launch_bounds__(256) void mma_gemm(
    const float* __restrict__ bias, float* __restrict__ C)
{
    extern __shared__ float smf[];
    float* As = smf;
    float* Bs = smf + 2 * STG_F;
    const uint32_t aAddr = smem_to_u32(As);
    const uint32_t bAddr = smem_to_u32(Bs);

    const int tid  = threadIdx.x;
    const int wid  = tid >> 5;
    const int lane = tid & 31;
    const int g    = lane >> 2;
    const int q    = lane & 3;
    const int wm   = wid & 1;
    const int wn   = wid >> 1;
    const int mBase = blockIdx.y * 128;
    const int nBase = blockIdx.x * 128;

    const float* Ag = (MODE == 0) ? g_Xr : g_Y;
    const float* Wg = (MODE == 0) ? g_Wqr : g_Wdr;

    float d[4][4][4];
    #pragma unroll
    for (int mt = 0; mt < 4; mt++)
        #pragma unroll
        for (int nt = 0; nt < 4; nt++)
            #pragma unroll
            for (int r = 0; r < 4; r++) d[mt][nt][r] = 0.f;

    auto load_stage = [&](int km, int buf) {
        uint32_t ad = aAddr + buf * (STG_F * 4);
        uint32_t bd = bAddr + buf * (STG_F * 4);
        const float* ap = Ag + (size_t)mBase * KDIM + km * 32;
        const float* wp = Wg + (size_t)nBase * KDIM + km * 32;
        #pragma unroll
        for (int t = 0; t < 4; t++) {
            int f4 = t * 256 + tid;
            int r = f4 >> 3, c = f4 & 7;
            cp_async16(ad + r * (GROW * 4) + c * 16, ap + (size_t)r * KDIM + c * 4);
            cp_async16(bd + r * (GROW * 4) + c * 16, wp + (size_t)r * KDIM + c * 4);
        }
        CP_COMMIT();
    };

    load_stage(0, 0);

    for (int km = 0; km < KDIM / 32; km++) {
        int buf = km & 1;
        if (km + 1 < KDIM / 32) {
            load_stage(km + 1, buf ^ 1);
            cp_wait<1>();
        } else {
            cp_wait<0>();
        }
        __syncthreads();

        const float* Ab = As + buf * STG_F + (wm * 64) * GROW;
        const float* Bb = Bs + buf * STG_F + (wn * 32) * GROW;
        #pragma unroll
        for (int kk = 0; kk < 4; kk++) {
            int kc = kk * 8 + q;
            uint32_t a[4][4], b[4][2];
            #pragma unroll
            for (int mt = 0; mt < 4; mt++) {
                const float* p = Ab + (mt * 16 + g) * GROW + kc;
                a[mt][0] = __float_as_uint(p[0]);
                a[mt][1] = __float_as_uint(p[8 * GROW]);
                a[mt][2] = __float_as_uint(p[4]);
                a[mt][3] = __float_as_uint(p[8 * GROW + 4]);
            }
            #pragma unroll
            for (int nt = 0; nt < 4; nt++) {
                const float* p = Bb + (nt * 8 + g) * GROW + kc;
                b[nt][0] = __float_as_uint(p[0]);
                b[nt][1] = __float_as_uint(p[4]);
            }
            #pragma unroll
            for (int mt = 0; mt < 4; mt++)
                #pragma unroll
                for (int nt = 0; nt < 4; nt++)
                    mma_tf32(d[mt][nt], a[mt], b[nt]);
        }
        __syncthreads();
    }

    #pragma unroll
    for (int mt = 0; mt < 4; mt++) {
        int m0 = mBase + wm * 64 + mt * 16 + g;
        #pragma unroll
        for (int nt = 0; nt < 4; nt++) {
            int n0 = nBase + wn * 32 + nt * 8 + 2 * q;
            float2 bb = *(const float2*)&bias[n0];
            float v0 = d[mt][nt][0] + bb.x;
            float v1 = d[mt][nt][1] + bb.y;
            float v2 = d[mt][nt][2] + bb.x;
            float v3 = d[mt][nt][3] + bb.y;
            if (MODE == 0) {
                scatter_qkv2(m0,     n0, v0, v1);
                scatter_qkv2(m0 + 8, n0, v2, v3);
            } else {
                *(float2*)&C[(size_t)m0 * E_ + n0]       = make_float2(v0, v1);
                *(float2*)&C[(size_t)(m0 + 8) * E_ + n0] = make_float2(v2, v3);
            }
        }
    }
}

// ---------------------------------------------------------------------------
// RoPE: rotate first ROT=32 dims of Q and K (inputs tf32-rounded, Q pre-scaled;
// rotation is linear so the scale commutes). Re-round outputs.
// ---------------------------------------------------------------------------
__global__ __launch_bounds__(256) void rope_kernel()
{
    int idx = blockIdx.x * blockDim.x + threadIdx.x;
    if (idx >= B_ * H_ * S_ * (ROT_ / 2)) return;
    int j  = idx & 15;
    int s  = (idx >> 4) & (S_ - 1);
    int bh = idx >> 15;

    float inv = powf(10000.0f, -((float)j) / 16.0f);
    float ang = (float)s * inv;
    float c  = cosf(ang);
    float sn = sinf(ang);

    size_t base = ((size_t)bh * S_ + s) * HS_;
    float* qp = &g_Q[base];
    float* kp = &g_K[base];

    float q0 = qp[j], q1 = qp[j + 16];
    qp[j]      = round_tf32(q0 * c - q1 * sn);
    qp[j + 16] = round_tf32(q1 * c + q0 * sn);

    float k0 = kp[j], k1 = kp[j + 16];
    kp[j]      = round_tf32(k0 * c - k1 * sn);
    kp[j + 16] = round_tf32(k1 * c + k0 * sn);
}

// ---------------------------------------------------------------------------
// Flash attention v2: mma.sync tf32 for S=QK^T and O+=PV.
// CTA: 128 q-rows; kv tiles of 64. 8 warps.
//  S phase: warp w owns q rows [16w,16w+16) (softmax warp-local).
//  PV phase: warps 2m x 4n; O frags 4x4 m16n8 tiles (64 regs).
// Smem strides 132/68 (==4 mod 32) -> conflict-free frag lds.
// ---------------------------------------------------------------------------
#define FQ 128
#define FKV 64
#define QSTR 132
#define PSTR 68
#define F_OFF_K (FQ * QSTR)               // 16896
#define F_OFF_V (F_OFF_K + FKV * QSTR)    // 25344
#define F_OFF_P (F_OFF_V + FKV * QSTR)    // 33792
#define F_OFF_A (F_OFF_P + FQ * PSTR)     // 42496
#define F_OFF_L (F_OFF_A + FQ)            // 42624
#define FLASH2_SMEM ((F_OFF_L + FQ) * 4)  // 171008 bytes

__global__ __launch_bounds__(256) void flash2_kernel()
{
    extern __shared__ float sm[];
    float* Qs = sm;
    float* Ks = sm + F_OFF_K;
    float* Vs = sm + F_OFF_V;
    float* Ps = sm + F_OFF_P;
    float* Al = sm + F_OFF_A;
    float* Ll = sm + F_OFF_L;
    const uint32_t sQ = smem_to_u32(Qs);
    const uint32_t sK = smem_to_u32(Ks);
    const uint32_t sV = smem_to_u32(Vs);

    const int tid  = threadIdx.x;
    const int wid  = tid >> 5;
    const int lane = tid & 31;
    const int g = lane >> 2, q = lane & 3;
    const int bh = blockIdx.y;
    const int qt = gridDim.x - 1 - blockIdx.x;     // big tiles first
    const int qBase = qt * FQ;
    const int wm = wid & 1, wn = wid >> 1;         // PV warp layout

    const float* Qg = g_Q + ((size_t)bh * S_ + qBase) * HS_;
    const float* Kg = g_K + (size_t)bh * S_ * HS_;
    const float* Vg = g_V + (size_t)bh * S_ * HS_;

    // prologue: Q tile (128x128) + K tile 0 (64x128)
    #pragma unroll
    for (int i = 0; i < 16; i++) {
        int f4 = i * 256 + tid;
        int r = f4 >> 5, c = (f4 & 31) << 2;
        cp_async16(sQ + (r * QSTR + c) * 4, Qg + r * HS_ + c);
    }
    #pragma unroll
    for (int i = 0; i < 8; i++) {
        int f4 = i * 256 + tid;
        int r = f4 >> 5, c = (f4 & 31) << 2;
        cp_async16(sK + (r * QSTR + c) * 4, Kg + r * HS_ + c);
    }
    CP_COMMIT();

    float m0 = -1e30f, m1 = -1e30f, l0 = 0.f, l1 = 0.f;
    float o[4][4][4];
    #pragma unroll
    for (int mt = 0; mt < 4; mt++)
        #pragma unroll
        for (int nt = 0; nt < 4; nt++)
            #pragma unroll
            for (int r = 0; r < 4; r++) o[mt][nt][r] = 0.f;

    const int srow0 = wid * 16 + g;     // S-strip row (and +8)
    const int ntiles = 2 * qt + 2;

    for (int t = 0; t < ntiles; t++) {
        cp_wait<0>();             // K(t) (and Q on t=0) arrived
        __syncthreads();          // + all warps done with V(t-1), Ps(t-1)

        // prefetch V(t) — covered by S phase
        {
            const float* Vt = Vg + (size_t)t * FKV * HS_;
            #pragma unroll
            for (int i = 0; i < 8; i++) {
                int f4 = i * 256 + tid;
                int r = f4 >> 5, c = (f4 & 31) << 2;
                cp_async16(sV + (r * QSTR + c) * 4, Vt + r * HS_ + c);
            }
            CP_COMMIT();
        }

        // ---- S = Q K^T for warp strip ----
        float s[8][4];
        #pragma unroll
        for (int nt = 0; nt < 8; nt++)
            #pragma unroll
            for (int r = 0; r < 4; r++) s[nt][r] = 0.f;

        const float* Aq = Qs + (size_t)(wid * 16 + g) * QSTR;
        #pragma unroll
        for (int kk = 0; kk < 16; kk++) {
            uint32_t a[4];
            const float* pa = Aq + kk * 8 + q;
            a[0] = __float_as_uint(pa[0]);
            a[1] = __float_as_uint(pa[8 * QSTR]);
            a[2] = __float_as_uint(pa[4]);
            a[3] = __float_as_uint(pa[8 * QSTR + 4]);
            #pragma unroll
            for (int nt = 0; nt < 8; nt++) {
                uint32_t b[2];
                const float* pb = Ks + (nt * 8 + g) * QSTR + kk * 8 + q;
                b[0] = __float_as_uint(pb[0]);
                b[1] = __float_as_uint(pb[4]);
                mma_tf32(s[nt], a, b);
            }
        }

        // ---- causal mask (diagonal tiles only) ----
        if (t >= 2 * qt) {
            int r0 = qBase + srow0, r1 = r0 + 8;
            #pragma unroll
            for (int nt = 0; nt < 8; nt++) {
                int c0 = t * FKV + nt * 8 + 2 * q;
                if (c0     > r0) s[nt][0] = -1e30f;
                if (c0 + 1 > r0) s[nt][1] = -1e30f;
                if (c0     > r1) s[nt][2] = -1e30f;
                if (c0 + 1 > r1) s[nt][3] = -1e30f;
            }
        }

        // ---- online softmax (rows srow0, srow0+8; reduce over quad) ----
        float rm0 = -1e30f, rm1 = -1e30f;
        #pragma unroll
        for (int nt = 0; nt < 8; nt++) {
            rm0 = fmaxf(rm0, fmaxf(s[nt][0], s[nt][1]));
            rm1 = fmaxf(rm1, fmaxf(s[nt][2], s[nt][3]));
        }
        rm0 = fmaxf(rm0, __shfl_xor_sync(0xffffffffu, rm0, 1));
        rm0 = fmaxf(rm0, __shfl_xor_sync(0xffffffffu, rm0, 2));
        rm1 = fmaxf(rm1, __shfl_xor_sync(0xffffffffu, rm1, 1));
        rm1 = fmaxf(rm1, __shfl_xor_sync(0xffffffffu, rm1, 2));
        float mn0 = fmaxf(m0, rm0), mn1 = fmaxf(m1, rm1);
        float al0 = __expf(m0 - mn0), al1 = __expf(m1 - mn1);
        float rs0 = 0.f, rs1 = 0.f;
        #pragma unroll
        for (int nt = 0; nt < 8; nt++) {
            float p0 = __expf(s[nt][0] - mn0);
            float p1 = __expf(s[nt][1] - mn0);
            float p2 = __expf(s[nt][2] - mn1);
            float p3 = __expf(s[nt][3] - mn1);
            rs0 += p0 + p1;
            rs1 += p2 + p3;
            int cl = nt * 8 + 2 * q;
            *(float2*)&Ps[(size_t)srow0 * PSTR + cl] =
                make_float2(round_tf32(p0), round_tf32(p1));
            *(float2*)&Ps[(size_t)(srow0 + 8) * PSTR + cl] =
                make_float2(round_tf32(p2), round_tf32(p3));
        }
        rs0 += __shfl_xor_sync(0xffffffffu, rs0, 1);
        rs0 += __shfl_xor_sync(0xffffffffu, rs0, 2);
        rs1 += __shfl_xor_sync(0xffffffffu, rs1, 1);
        rs1 += __shfl_xor_sync(0xffffffffu, rs1, 2);
        l0 = l0 * al0 + rs0;
        l1 = l1 * al1 + rs1;
        m0 = mn0; m1 = mn1;
        if (q == 0) { Al[srow0] = al0; Al[srow0 + 8] = al1; }

        cp_wait<0>();             // V(t) arrived
        __syncthreads();          // Ps/Al visible; K buffer free

        // prefetch K(t+1) — covered by PV phase
        if (t + 1 < ntiles) {
            const float* Kt = Kg + (size_t)(t + 1) * FKV * HS_;
            #pragma unroll
            for (int i = 0; i < 8; i++) {
                int f4 = i * 256 + tid;
                int r = f4 >> 5, c = (f4 & 31) << 2;
                cp_async16(sK + (r * QSTR + c) * 4, Kt + r * HS_ + c);
            }
            CP_COMMIT();
        }

        // ---- O rescale + O += P V ----
        #pragma unroll
        for (int mt = 0; mt < 4; mt++) {
            float a0 = Al[wm * 64 + mt * 16 + g];
            float a1 = Al[wm * 64 + mt * 16 + g + 8];
            #pragma unroll
            for (int nt = 0; nt < 4; nt++) {
                o[mt][nt][0] *= a0; o[mt][nt][1] *= a0;
                o[mt][nt][2] *= a1; o[mt][nt][3] *= a1;
            }
        }
        #pragma unroll
        for (int kk = 0; kk < 8; kk++) {
            uint32_t pa[4][4];
            #pragma unroll
            for (int mt = 0; mt < 4; mt++) {
                const float* pp = Ps + (size_t)(wm * 64 + mt * 16 + g) * PSTR + kk * 8 + q;
                pa[mt][0] = __float_as_uint(pp[0]);
                pa[mt][1] = __float_as_uint(pp[8 * PSTR]);
                pa[mt][2] = __float_as_uint(pp[4]);
                pa[mt][3] = __float_as_uint(pp[8 * PSTR + 4]);
            }
            #pragma unroll
            for (int nt = 0; nt < 4; nt++) {
                uint32_t b[2];
                const float* pv = Vs + (size_t)(kk * 8 + q) * QSTR + wn * 32 + nt * 8 + g;
                b[0] = __float_as_uint(pv[0]);
                b[1] = __float_as_uint(pv[4 * QSTR]);
                #pragma unroll
                for (int mt = 0; mt < 4; mt++)
                    mma_tf32(o[mt][nt], pa[mt], b);
            }
        }
    }

    // ---- writeout: normalize by 1/l, round, store to g_Y [B,S,E] ----
    if (q == 0) { Ll[srow0] = l0; Ll[srow0 + 8] = l1; }
    __syncthreads();
    int b = bh >> 4, h = bh & 15;
    #pragma unroll
    for (int mt = 0; mt < 4; mt++) {
        int r0 = wm * 64 + mt * 16 + g;
        float i0 = 1.f / Ll[r0];
        float i1 = 1.f / Ll[r0 + 8];
        float* Y0 = g_Y + ((size_t)b * S_ + qBase + r0) * E_ + h * HS_;
        float* Y1 = Y0 + 8 * E_;
        #pragma unroll
        for (int nt = 0; nt < 4; nt++) {
            int c0 = wn * 32 + nt * 8 + 2 * q;
            *(float2*)&Y0[c0] = make_float2(round_tf32(o[mt][nt][0] * i0),
                                            round_tf32(o[mt][nt][1] * i0));
            *(float2*)&Y1[c0] = make_float2(round_tf32(o[mt][nt][2] * i1),
                                            round_tf32(o[mt][nt][3] * i1));
        }
    }
}

// ---------------------------------------------------------------------------
// Launch
// ---------------------------------------------------------------------------
extern "C" void kernel_launch(void* const* d_in, const int* in_sizes, int n_in,
                              void* d_out, int out_size)
{
    const float* x       = (const float*)d_in[0];
    const float* w_qkv   = (const float*)d_in[1];
    const float* b_qkv   = (const float*)d_in[2];
    const float* w_dense = (const float*)d_in[3];
    const float* b_dense = (const float*)d_in[4];
    float* out = (float*)d_out;

    cudaFuncSetAttribute(mma_gemm<0>, cudaFuncAttributeMaxDynamicSharedMemorySize, GEMM_SMEM);
    cudaFuncSetAttribute(mma_gemm<1>, cudaFuncAttributeMaxDynamicSharedMemorySize, GEMM_SMEM);
    cudaFuncSetAttribute(flash2_kernel, cudaFuncAttributeMaxDynamicSharedMemorySize, FLASH2_SMEM);

    // 0. Round GEMM inputs to tf32 (RN)
    round_kernel<<<(M_ * E_ / 4 + 255) / 256, 256>>>(x, 0, M_ * E_ / 4);
    round_kernel<<<(NQKV * E_ / 4 + 255) / 256, 256>>>(w_qkv, 1, NQKV * E_ / 4);
    round_kernel<<<(E_ * E_ / 4 + 255) / 256, 256>>>(w_dense, 2, E_ * E_ / 4);

    // 1. QKV projection + bias -> Q (scaled) / K / V, tf32-rounded
    mma_gemm<0><<<dim3(NQKV / 128, M_ / 128), 256, GEMM_SMEM>>>(b_qkv, nullptr);

    // 2. RoPE on first 32 dims of Q and K
    rope_kernel<<<(B_ * H_ * S_ * (ROT_ / 2)) / 256, 256>>>();

    // 3. Causal flash attention (mma.sync tf32) -> g_Y
    flash2_kernel<<<dim3(S_ / FQ, B_ * H_), 256, FLASH2_SMEM>>>();

    // 4. Dense projection + bias -> output
    mma_gemm<1><<<dim3(E_ / 128, M_ / 128), 256, GEMM_SMEM>>>(b_dense, out);
}

// round 10
// speedup vs baseline: 3.1974x; 1.0235x over previous
#include <cuda_runtime.h>
#include <math.h>
#include <stdint.h>

// Problem constants
#define B_   2
#define S_   2048
#define E_   2048
#define H_   16
#define HS_  128
#define M_   (B_ * S_)      // 4096
#define NQKV (3 * E_)       // 6144
#define KDIM E_             // 2048
#define ROT_ 32
#define QSCALE 0.08838834764831845f   // 1/sqrt(128)

// Scratch (device globals: no allocations allowed)
__device__ float g_Q[(size_t)B_ * H_ * S_ * HS_];   // pre-scaled by QSCALE, tf32-rounded
__device__ float g_K[(size_t)B_ * H_ * S_ * HS_];   // tf32-rounded
__device__ float g_V[(size_t)B_ * H_ * S_ * HS_];   // tf32-rounded
__device__ float g_Y[(size_t)B_ * S_ * E_];         // flash output, tf32-rounded
__device__ float g_Xr[(size_t)M_ * E_];             // x rounded to tf32
__device__ float g_Wqr[(size_t)NQKV * E_];          // w_qkv rounded to tf32
__device__ float g_Wdr[(size_t)E_ * E_];            // w_dense rounded to tf32

// ---------------------------------------------------------------------------
// Helpers
// ---------------------------------------------------------------------------
__device__ __forceinline__ uint32_t smem_to_u32(const void* p) {
    uint32_t a;
    asm("{ .reg .u64 t; cvta.to.shared.u64 t, %1; cvt.u32.u64 %0, t; }"
        : "=r"(a) : "l"(p));
    return a;
}

__device__ __forceinline__ void cp_async16(uint32_t dst, const void* src) {
    asm volatile("cp.async.cg.shared.global [%0], [%1], 16;" :: "r"(dst), "l"(src));
}
#define CP_COMMIT() asm volatile("cp.async.commit_group;" ::: "memory")
template <int N>
__device__ __forceinline__ void cp_wait() {
    asm volatile("cp.async.wait_group %0;" :: "n"(N) : "memory");
}

__device__ __forceinline__ float round_tf32(float x) {
    uint32_t b;
    asm("cvt.rna.tf32.f32 %0, %1;" : "=r"(b) : "f"(x));
    return __uint_as_float(b);
}

// mma.sync m16n8k8 tf32: D = A(16x8,row) * B(8x8,col) + D
__device__ __forceinline__ void mma_tf32(float* d, const uint32_t* a, const uint32_t* b) {
    asm volatile(
        "mma.sync.aligned.m16n8k8.row.col.f32.tf32.tf32.f32 "
        "{%0,%1,%2,%3}, {%4,%5,%6,%7}, {%8,%9}, {%0,%1,%2,%3};"
        : "+f"(d[0]), "+f"(d[1]), "+f"(d[2]), "+f"(d[3])
        : "r"(a[0]), "r"(a[1]), "r"(a[2]), "r"(a[3]), "r"(b[0]), "r"(b[1]));
}

// ---------------------------------------------------------------------------
// Round fp32 -> tf32 (RN) into device-global copies
// ---------------------------------------------------------------------------
__global__ __launch_bounds__(256) void round_kernel(const float* __restrict__ src,
                                                    int which, int n4)
{
    float* dst = (which == 0) ? g_Xr : (which == 1) ? g_Wqr : g_Wdr;
    int i = blockIdx.x * blockDim.x + threadIdx.x;
    if (i >= n4) return;
    float4 v = ((const float4*)src)[i];
    v.x = round_tf32(v.x); v.y = round_tf32(v.y);
    v.z = round_tf32(v.z); v.w = round_tf32(v.w);
    ((float4*)dst)[i] = v;
}

// ---------------------------------------------------------------------------
// mma.sync tf32 GEMM: C[m,n] = sum_k A[m,k] * W[n,k] + bias[n]
// MODE 0: A=g_Xr, W=g_Wqr, scatter (round + Q-scale) into g_Q/g_K/g_V
// MODE 1: A=g_Y,  W=g_Wdr, write C
// CTA 128x128, BK=32, 8 warps (2m x 4n), warp tile 64x32.
// 3-stage circular cp.async pipeline, ONE __syncthreads per chunk:
//   wait(stage km) -> barrier -> issue(stage km+2) -> compute(km)
// WAR-safe: buf (km+2)%3 last read at chunk km-1; all warps passed this
// chunk's barrier (i.e., finished km-1) before any issue.
// ---------------------------------------------------------------------------
#define GROW 36
#define STG_F (128 * GROW)                // floats per operand-stage (4608)
#define NSTG 3
#define GEMM_SMEM (2 * NSTG * STG_F * 4)  // 110592 bytes
#define KCH (KDIM / 32)                   // 64

__device__ __forceinline__ void scatter_qkv2(int m, int n, float v0, float v1) {
    int b = m >> 11;
    int srow = m & (S_ - 1);
    int h = n / 384;
    int c = n % 384;
    size_t base = ((size_t)(b * H_ + h) * S_ + srow) * HS_;
    float* dst;
    if (c < HS_) {
        dst = g_Q + base + c;
        v0 *= QSCALE; v1 *= QSCALE;
    } else if (c < 2 * HS_) {
        dst = g_K + base + (c - HS_);
    } else {
        dst = g_V + base + (c - 2 * HS_);
    }
    *(float2*)dst = make_float2(round_tf32(v0), round_tf32(v1));
}

template <int MODE>
__global__ __launch_bounds__(256, 2) void mma_gemm(
    const float* __restrict__ bias, float* __restrict__ C)
{
    extern __shared__ float smf[];
    float* As = smf;                      // [NSTG][128][GROW]
    float* Bs = smf + NSTG * STG_F;       // [NSTG][128][GROW]
    const uint32_t aAddr = smem_to_u32(As);
    const uint32_t bAddr = smem_to_u32(Bs);

    const int tid  = threadIdx.x;
    const int wid  = tid >> 5;
    const int lane = tid & 31;
    const int g    = lane >> 2;
    const int q    = lane & 3;
    const int wm   = wid & 1;
    const int wn   = wid >> 1;
    const int mBase = blockIdx.y * 128;
    const int nBase = blockIdx.x * 128;

    const float* Ag = (MODE == 0) ? g_Xr : g_Y;
    const float* Wg = (MODE == 0) ? g_Wqr : g_Wdr;

    float d[4][4][4];
    #pragma unroll
    for (int mt = 0; mt < 4; mt++)
        #pragma unroll
        for (int nt = 0; nt < 4; nt++)
            #pragma unroll
            for (int r = 0; r < 4; r++) d[mt][nt][r] = 0.f;

    auto load_stage = [&](int km) {
        int buf = km % NSTG;
        uint32_t ad = aAddr + buf * (STG_F * 4);
        uint32_t bd = bAddr + buf * (STG_F * 4);
        const float* ap = Ag + (size_t)mBase * KDIM + km * 32;
        const float* wp = Wg + (size_t)nBase * KDIM + km * 32;
        #pragma unroll
        for (int t = 0; t < 4; t++) {
            int f4 = t * 256 + tid;
            int r = f4 >> 3, c = f4 & 7;
            cp_async16(ad + r * (GROW * 4) + c * 16, ap + (size_t)r * KDIM + c * 4);
            cp_async16(bd + r * (GROW * 4) + c * 16, wp + (size_t)r * KDIM + c * 4);
        }
        CP_COMMIT();
    };

    // prologue: stages 0, 1
    load_stage(0);
    load_stage(1);

    for (int km = 0; km < KCH; km++) {
        // stage km complete? (groups committed so far: 0..km+1)
        if (km + 2 <= KCH - 1) cp_wait<1>();
        else                   cp_wait<0>();
        __syncthreads();                 // data visible + all warps done with km-1

        if (km + 2 < KCH) load_stage(km + 2);

        int buf = km % NSTG;
        const float* Ab = As + buf * STG_F + (wm * 64) * GROW;
        const float* Bb = Bs + buf * STG_F + (wn * 32) * GROW;
        #pragma unroll
        for (int kk = 0; kk < 4; kk++) {
            int kc = kk * 8 + q;
            uint32_t a[4][4], b[4][2];
            #pragma unroll
            for (int mt = 0; mt < 4; mt++) {
                const float* p = Ab + (mt * 16 + g) * GROW + kc;
                a[mt][0] = __float_as_uint(p[0]);
                a[mt][1] = __float_as_uint(p[8 * GROW]);
                a[mt][2] = __float_as_uint(p[4]);
                a[mt][3] = __float_as_uint(p[8 * GROW + 4]);
            }
            #pragma unroll
            for (int nt = 0; nt < 4; nt++) {
                const float* p = Bb + (nt * 8 + g) * GROW + kc;
                b[nt][0] = __float_as_uint(p[0]);
                b[nt][1] = __float_as_uint(p[4]);
            }
            #pragma unroll
            for (int mt = 0; mt < 4; mt++)
                #pragma unroll
                for (int nt = 0; nt < 4; nt++)
                    mma_tf32(d[mt][nt], a[mt], b[nt]);
        }
    }

    // epilogue (registers only; no smem -> no trailing sync needed)
    #pragma unroll
    for (int mt = 0; mt < 4; mt++) {
        int m0 = mBase + wm * 64 + mt * 16 + g;
        #pragma unroll
        for (int nt = 0; nt < 4; nt++) {
            int n0 = nBase + wn * 32 + nt * 8 + 2 * q;
            float2 bb = *(const float2*)&bias[n0];
            float v0 = d[mt][nt][0] + bb.x;
            float v1 = d[mt][nt][1] + bb.y;
            float v2 = d[mt][nt][2] + bb.x;
            float v3 = d[mt][nt][3] + bb.y;
            if (MODE == 0) {
                scatter_qkv2(m0,     n0, v0, v1);
                scatter_qkv2(m0 + 8, n0, v2, v3);
            } else {
                *(float2*)&C[(size_t)m0 * E_ + n0]       = make_float2(v0, v1);
                *(float2*)&C[(size_t)(m0 + 8) * E_ + n0] = make_float2(v2, v3);
            }
        }
    }
}

// ---------------------------------------------------------------------------
// RoPE: rotate first ROT=32 dims of Q and K; re-round outputs.
// ---------------------------------------------------------------------------
__global__ __launch_bounds__(256) void rope_kernel()
{
    int idx = blockIdx.x * blockDim.x + threadIdx.x;
    if (idx >= B_ * H_ * S_ * (ROT_ / 2)) return;
    int j  = idx & 15;
    int s  = (idx >> 4) & (S_ - 1);
    int bh = idx >> 15;

    float inv = powf(10000.0f, -((float)j) / 16.0f);
    float ang = (float)s * inv;
    float c  = cosf(ang);
    float sn = sinf(ang);

    size_t base = ((size_t)bh * S_ + s) * HS_;
    float* qp = &g_Q[base];
    float* kp = &g_K[base];

    float q0 = qp[j], q1 = qp[j + 16];
    qp[j]      = round_tf32(q0 * c - q1 * sn);
    qp[j + 16] = round_tf32(q1 * c + q0 * sn);

    float k0 = kp[j], k1 = kp[j + 16];
    kp[j]      = round_tf32(k0 * c - k1 * sn);
    kp[j + 16] = round_tf32(k1 * c + k0 * sn);
}

// ---------------------------------------------------------------------------
// Flash attention v2: mma.sync tf32 for S=QK^T and O+=PV. (unchanged)
// ---------------------------------------------------------------------------
#define FQ 128
#define FKV 64
#define QSTR 132
#define PSTR 68
#define F_OFF_K (FQ * QSTR)
#define F_OFF_V (F_OFF_K + FKV * QSTR)
#define F_OFF_P (F_OFF_V + FKV * QSTR)
#define F_OFF_A (F_OFF_P + FQ * PSTR)
#define F_OFF_L (F_OFF_A + FQ)
#define FLASH2_SMEM ((F_OFF_L + FQ) * 4)  // 171008 bytes

__global__ __launch_bounds__(256) void flash2_kernel()
{
    extern __shared__ float sm[];
    float* Qs = sm;
    float* Ks = sm + F_OFF_K;
    float* Vs = sm + F_OFF_V;
    float* Ps = sm + F_OFF_P;
    float* Al = sm + F_OFF_A;
    float* Ll = sm + F_OFF_L;
    const uint32_t sQ = smem_to_u32(Qs);
    const uint32_t sK = smem_to_u32(Ks);
    const uint32_t sV = smem_to_u32(Vs);

    const int tid  = threadIdx.x;
    const int wid  = tid >> 5;
    const int lane = tid & 31;
    const int g = lane >> 2, q = lane & 3;
    const int bh = blockIdx.y;
    const int qt = gridDim.x - 1 - blockIdx.x;
    const int qBase = qt * FQ;
    const int wm = wid & 1, wn = wid >> 1;

    const float* Qg = g_Q + ((size_t)bh * S_ + qBase) * HS_;
    const float* Kg = g_K + (size_t)bh * S_ * HS_;
    const float* Vg = g_V + (size_t)bh * S_ * HS_;

    #pragma unroll
    for (int i = 0; i < 16; i++) {
        int f4 = i * 256 + tid;
        int r = f4 >> 5, c = (f4 & 31) << 2;
        cp_async16(sQ + (r * QSTR + c) * 4, Qg + r * HS_ + c);
    }
    #pragma unroll
    for (int i = 0; i < 8; i++) {
        int f4 = i * 256 + tid;
        int r = f4 >> 5, c = (f4 & 31) << 2;
        cp_async16(sK + (r * QSTR + c) * 4, Kg + r * HS_ + c);
    }
    CP_COMMIT();

    float m0 = -1e30f, m1 = -1e30f, l0 = 0.f, l1 = 0.f;
    float o[4][4][4];
    #pragma unroll
    for (int mt = 0; mt < 4; mt++)
        #pragma unroll
        for (int nt = 0; nt < 4; nt++)
            #pragma unroll
            for (int r = 0; r < 4; r++) o[mt][nt][r] = 0.f;

    const int srow0 = wid * 16 + g;
    const int ntiles = 2 * qt + 2;

    for (int t = 0; t < ntiles; t++) {
        cp_wait<0>();
        __syncthreads();

        {
            const float* Vt = Vg + (size_t)t * FKV * HS_;
            #pragma unroll
            for (int i = 0; i < 8; i++) {
                int f4 = i * 256 + tid;
                int r = f4 >> 5, c = (f4 & 31) << 2;
                cp_async16(sV + (r * QSTR + c) * 4, Vt + r * HS_ + c);
            }
            CP_COMMIT();
        }

        float s[8][4];
        #pragma unroll
        for (int nt = 0; nt < 8; nt++)
            #pragma unroll
            for (int r = 0; r < 4; r++) s[nt][r] = 0.f;

        const float* Aq = Qs + (size_t)(wid * 16 + g) * QSTR;
        #pragma unroll
        for (int kk = 0; kk < 16; kk++) {
            uint32_t a[4];
            const float* pa = Aq + kk * 8 + q;
            a[0] = __float_as_uint(pa[0]);
            a[1] = __float_as_uint(pa[8 * QSTR]);
            a[2] = __float_as_uint(pa[4]);
            a[3] = __float_as_uint(pa[8 * QSTR + 4]);
            #pragma unroll
            for (int nt = 0; nt < 8; nt++) {
                uint32_t b[2];
                const float* pb = Ks + (nt * 8 + g) * QSTR + kk * 8 + q;
                b[0] = __float_as_uint(pb[0]);
                b[1] = __float_as_uint(pb[4]);
                mma_tf32(s[nt], a, b);
            }
        }

        if (t >= 2 * qt) {
            int r0 = qBase + srow0, r1 = r0 + 8;
            #pragma unroll
            for (int nt = 0; nt < 8; nt++) {
                int c0 = t * FKV + nt * 8 + 2 * q;
                if (c0     > r0) s[nt][0] = -1e30f;
                if (c0 + 1 > r0) s[nt][1] = -1e30f;
                if (c0     > r1) s[nt][2] = -1e30f;
                if (c0 + 1 > r1) s[nt][3] = -1e30f;
            }
        }

        float rm0 = -1e30f, rm1 = -1e30f;
        #pragma unroll
        for (int nt = 0; nt < 8; nt++) {
            rm0 = fmaxf(rm0, fmaxf(s[nt][0], s[nt][1]));
            rm1 = fmaxf(rm1, fmaxf(s[nt][2], s[nt][3]));
        }
        rm0 = fmaxf(rm0, __shfl_xor_sync(0xffffffffu, rm0, 1));
        rm0 = fmaxf(rm0, __shfl_xor_sync(0xffffffffu, rm0, 2));
        rm1 = fmaxf(rm1, __shfl_xor_sync(0xffffffffu, rm1, 1));
        rm1 = fmaxf(rm1, __shfl_xor_sync(0xffffffffu, rm1, 2));
        float mn0 = fmaxf(m0, rm0), mn1 = fmaxf(m1, rm1);
        float al0 = __expf(m0 - mn0), al1 = __expf(m1 - mn1);
        float rs0 = 0.f, rs1 = 0.f;
        #pragma unroll
        for (int nt = 0; nt < 8; nt++) {
            float p0 = __expf(s[nt][0] - mn0);
            float p1 = __expf(s[nt][1] - mn0);
            float p2 = __expf(s[nt][2] - mn1);
            float p3 = __expf(s[nt][3] - mn1);
            rs0 += p0 + p1;
            rs1 += p2 + p3;
            int cl = nt * 8 + 2 * q;
            *(float2*)&Ps[(size_t)srow0 * PSTR + cl] =
                make_float2(round_tf32(p0), round_tf32(p1));
            *(float2*)&Ps[(size_t)(srow0 + 8) * PSTR + cl] =
                make_float2(round_tf32(p2), round_tf32(p3));
        }
        rs0 += __shfl_xor_sync(0xffffffffu, rs0, 1);
        rs0 += __shfl_xor_sync(0xffffffffu, rs0, 2);
        rs1 += __shfl_xor_sync(0xffffffffu, rs1, 1);
        rs1 += __shfl_xor_sync(0xffffffffu, rs1, 2);
        l0 = l0 * al0 + rs0;
        l1 = l1 * al1 + rs1;
        m0 = mn0; m1 = mn1;
        if (q == 0) { Al[srow0] = al0; Al[srow0 + 8] = al1; }

        cp_wait<0>();
        __syncthreads();

        if (t + 1 < ntiles) {
            const float* Kt = Kg + (size_t)(t + 1) * FKV * HS_;
            #pragma unroll
            for (int i = 0; i < 8; i++) {
                int f4 = i * 256 + tid;
                int r = f4 >> 5, c = (f4 & 31) << 2;
                cp_async16(sK + (r * QSTR + c) * 4, Kt + r * HS_ + c);
            }
            CP_COMMIT();
        }

        #pragma unroll
        for (int mt = 0; mt < 4; mt++) {
            float a0 = Al[wm * 64 + mt * 16 + g];
            float a1 = Al[wm * 64 + mt * 16 + g + 8];
            #pragma unroll
            for (int nt = 0; nt < 4; nt++) {
                o[mt][nt][0] *= a0; o[mt][nt][1] *= a0;
                o[mt][nt][2] *= a1; o[mt][nt][3] *= a1;
            }
        }
        #pragma unroll
        for (int kk = 0; kk < 8; kk++) {
            uint32_t pa[4][4];
            #pragma unroll
            for (int mt = 0; mt < 4; mt++) {
                const float* pp = Ps + (size_t)(wm * 64 + mt * 16 + g) * PSTR + kk * 8 + q;
                pa[mt][0] = __float_as_uint(pp[0]);
                pa[mt][1] = __float_as_uint(pp[8 * PSTR]);
                pa[mt][2] = __float_as_uint(pp[4]);
                pa[mt][3] = __float_as_uint(pp[8 * PSTR + 4]);
            }
            #pragma unroll
            for (int nt = 0; nt < 4; nt++) {
                uint32_t b[2];
                const float* pv = Vs + (size_t)(kk * 8 + q) * QSTR + wn * 32 + nt * 8 + g;
                b[0] = __float_as_uint(pv[0]);
                b[1] = __float_as_uint(pv[4 * QSTR]);
                #pragma unroll
                for (int mt = 0; mt < 4; mt++)
                    mma_tf32(o[mt][nt], pa[mt], b);
            }
        }
    }

    if (q == 0) { Ll[srow0] = l0; Ll[srow0 + 8] = l1; }
    __syncthreads();
    int b = bh >> 4, h = bh & 15;
    #pragma unroll
    for (int mt = 0; mt < 4; mt++) {
        int r0 = wm * 64 + mt * 16 + g;
        float i0 = 1.f / Ll[r0];
        float i1 = 1.f / Ll[r0 + 8];
        float* Y0 = g_Y + ((size_t)b * S_ + qBase + r0) * E_ + h * HS_;
        float* Y1 = Y0 + 8 * E_;
        #pragma unroll
        for (int nt = 0; nt < 4; nt++) {
            int c0 = wn * 32 + nt * 8 + 2 * q;
            *(float2*)&Y0[c0] = make_float2(round_tf32(o[mt][nt][0] * i0),
                                            round_tf32(o[mt][nt][1] * i0));
            *(float2*)&Y1[c0] = make_float2(round_tf32(o[mt][nt][2] * i1),
                                            round_tf32(o[mt][nt][3] * i1));
        }
    }
}

// ---------------------------------------------------------------------------
// Launch
// ---------------------------------------------------------------------------
extern "C" void kernel_launch(void* const* d_in, const int* in_sizes, int n_in,
                              void* d_out, int out_size)
{
    const float* x       = (const float*)d_in[0];
    const float* w_qkv   = (const float*)d_in[1];
    const float* b_qkv   = (const float*)d_in[2];
    const float* w_dense = (const float*)d_in[3];
    const float* b_dense = (const float*)d_in[4];
    float* out = (float*)d_out;

    cudaFuncSetAttribute(mma_gemm<0>, cudaFuncAttributeMaxDynamicSharedMemorySize, GEMM_SMEM);
    cudaFuncSetAttribute(mma_gemm<1>, cudaFuncAttributeMaxDynamicSharedMemorySize, GEMM_SMEM);
    cudaFuncSetAttribute(flash2_kernel, cudaFuncAttributeMaxDynamicSharedMemorySize, FLASH2_SMEM);

    // 0. Round GEMM inputs to tf32 (RN)
    round_kernel<<<(M_ * E_ / 4 + 255) / 256, 256>>>(x, 0, M_ * E_ / 4);
    round_kernel<<<(NQKV * E_ / 4 + 255) / 256, 256>>>(w_qkv, 1, NQKV * E_ / 4);
    round_kernel<<<(E_ * E_ / 4 + 255) / 256, 256>>>(w_dense, 2, E_ * E_ / 4);

    // 1. QKV projection + bias -> Q (scaled) / K / V, tf32-rounded
    mma_gemm<0><<<dim3(NQKV / 128, M_ / 128), 256, GEMM_SMEM>>>(b_qkv, nullptr);

    // 2. RoPE on first 32 dims of Q and K
    rope_kernel<<<(B_ * H_ * S_ * (ROT_ / 2)) / 256, 256>>>();

    // 3. Causal flash attention (mma.sync tf32) -> g_Y
    flash2_kernel<<<dim3(S_ / FQ, B_ * H_), 256, FLASH2_SMEM>>>();

    // 4. Dense projection + bias -> output
    mma_gemm<1><<<dim3(E_ / 128, M_ / 128), 256, GEMM_SMEM>>>(b_dense, out);
}

// round 12
// speedup vs baseline: 5.9150x; 1.8499x over previous
#include <cuda_runtime.h>
#include <cuda_fp16.h>
#include <math.h>
#include <stdint.h>

// Problem constants
#define B_   2
#define S_   2048
#define E_   2048
#define H_   16
#define HS_  128
#define M_   (B_ * S_)      // 4096
#define NQKV (3 * E_)       // 6144
#define KDIM E_             // 2048
#define ROT_ 32
#define QSCALE 0.08838834764831845f   // 1/sqrt(128)

// Scratch (device globals; fp16 storage, fp32 accumulate)
__device__ __align__(16) __half g_Qh[(size_t)B_ * H_ * S_ * HS_];  // [bh][s][d], pre-scaled
__device__ __align__(16) __half g_Kh[(size_t)B_ * H_ * S_ * HS_];  // [bh][s][d]
__device__ __align__(16) __half g_Vt[(size_t)B_ * H_ * HS_ * S_];  // [bh][d][s]  (transposed!)
__device__ __align__(16) __half g_Yh[(size_t)M_ * E_];             // flash output
__device__ __align__(16) __half g_Xh[(size_t)M_ * E_];
__device__ __align__(16) __half g_Wqh[(size_t)NQKV * E_];
__device__ __align__(16) __half g_Wdh[(size_t)E_ * E_];

// ---------------------------------------------------------------------------
// Helpers
// ---------------------------------------------------------------------------
__device__ __forceinline__ uint32_t smem_to_u32(const void* p) {
    uint32_t a;
    asm("{ .reg .u64 t; cvta.to.shared.u64 t, %1; cvt.u32.u64 %0, t; }"
        : "=r"(a) : "l"(p));
    return a;
}

__device__ __forceinline__ void cp_async16(uint32_t dst, const void* src) {
    asm volatile("cp.async.cg.shared.global [%0], [%1], 16;" :: "r"(dst), "l"(src));
}
#define CP_COMMIT() asm volatile("cp.async.commit_group;" ::: "memory")
template <int N>
__device__ __forceinline__ void cp_wait() {
    asm volatile("cp.async.wait_group %0;" :: "n"(N) : "memory");
}

// mma.sync m16n8k16 fp16 in / fp32 accum
__device__ __forceinline__ void mma_f16(float* d, const uint32_t* a, const uint32_t* b) {
    asm volatile(
        "mma.sync.aligned.m16n8k16.row.col.f32.f16.f16.f32 "
        "{%0,%1,%2,%3}, {%4,%5,%6,%7}, {%8,%9}, {%0,%1,%2,%3};"
        : "+f"(d[0]), "+f"(d[1]), "+f"(d[2]), "+f"(d[3])
        : "r"(a[0]), "r"(a[1]), "r"(a[2]), "r"(a[3]), "r"(b[0]), "r"(b[1]));
}

// ---------------------------------------------------------------------------
// Convert fp32 -> fp16 (RN); which: 0 -> g_Xh, 1 -> g_Wqh, 2 -> g_Wdh
// ---------------------------------------------------------------------------
__global__ __launch_bounds__(256) void convert_kernel(const float* __restrict__ src,
                                                      int which, int n8)
{
    __half* dst = (which == 0) ? g_Xh : (which == 1) ? g_Wqh : g_Wdh;
    int i = blockIdx.x * blockDim.x + threadIdx.x;
    if (i >= n8) return;
    float4 u = ((const float4*)src)[(size_t)i * 2];
    float4 v = ((const float4*)src)[(size_t)i * 2 + 1];
    __half2 h0 = __floats2half2_rn(u.x, u.y);
    __half2 h1 = __floats2half2_rn(u.z, u.w);
    __half2 h2 = __floats2half2_rn(v.x, v.y);
    __half2 h3 = __floats2half2_rn(v.z, v.w);
    uint4 o;
    o.x = *(uint32_t*)&h0; o.y = *(uint32_t*)&h1;
    o.z = *(uint32_t*)&h2; o.w = *(uint32_t*)&h3;
    *(uint4*)(dst + (size_t)i * 8) = o;
}

// ---------------------------------------------------------------------------
// fp16 mma GEMM: C[m,n] = sum_k A[m,k]*W[n,k] + bias[n]
// MODE 0: A=g_Xh, W=g_Wqh -> scatter (scale+convert) into g_Qh/g_Kh/g_Vt
// MODE 1: A=g_Yh, W=g_Wdh -> write fp32 C
// CTA 128x128, BK=64 (4 k16 steps), 8 warps (2m x 4n), warp 64x32.
// 3-stage circular cp.async pipeline, one __syncthreads per chunk.
// Rows 72 halfs (144 B): frag lds banks (4g+q) -> conflict-free.
// ---------------------------------------------------------------------------
#define GROWH 72
#define STG_H (128 * GROWH)               // halfs per operand-stage (9216)
#define NSTG 3
#define GEMM_SMEM (2 * NSTG * STG_H * 2)  // 110592 bytes
#define KCH (KDIM / 64)                   // 32

__device__ __forceinline__ void scatter_qkv2(int m, int n, float v0, float v1) {
    int b = m >> 11;
    int srow = m & (S_ - 1);
    int h = n / 384;
    int c = n % 384;
    int bh = b * H_ + h;
    if (c < HS_) {
        size_t base = ((size_t)bh * S_ + srow) * HS_ + c;
        *(__half2*)&g_Qh[base] = __floats2half2_rn(v0 * QSCALE, v1 * QSCALE);
    } else if (c < 2 * HS_) {
        size_t base = ((size_t)bh * S_ + srow) * HS_ + (c - HS_);
        *(__half2*)&g_Kh[base] = __floats2half2_rn(v0, v1);
    } else {
        int dd = c - 2 * HS_;
        size_t tb = ((size_t)bh * HS_ + dd) * S_ + srow;   // transposed [d][s]
        g_Vt[tb]      = __float2half_rn(v0);
        g_Vt[tb + S_] = __float2half_rn(v1);
    }
}

template <int MODE>
__global__ __launch_bounds__(256, 2) void mma_gemm(
    const float* __restrict__ bias, float* __restrict__ C)
{
    extern __shared__ __half smh[];
    __half* As = smh;                      // [NSTG][128][GROWH]
    __half* Bs = smh + NSTG * STG_H;
    const uint32_t aAddr = smem_to_u32(As);
    const uint32_t bAddr = smem_to_u32(Bs);

    const int tid  = threadIdx.x;
    const int wid  = tid >> 5;
    const int lane = tid & 31;
    const int g    = lane >> 2;
    const int q    = lane & 3;
    const int wm   = wid & 1;
    const int wn   = wid >> 1;
    const int mBase = blockIdx.y * 128;
    const int nBase = blockIdx.x * 128;

    const __half* Ag = (MODE == 0) ? g_Xh : g_Yh;
    const __half* Wg = (MODE == 0) ? g_Wqh : g_Wdh;

    float d[4][4][4];
    #pragma unroll
    for (int mt = 0; mt < 4; mt++)
        #pragma unroll
        for (int nt = 0; nt < 4; nt++)
            #pragma unroll
            for (int r = 0; r < 4; r++) d[mt][nt][r] = 0.f;

    auto load_stage = [&](int km) {
        int buf = km % NSTG;
        uint32_t ad = aAddr + buf * (STG_H * 2);
        uint32_t bd = bAddr + buf * (STG_H * 2);
        const __half* ap = Ag + (size_t)mBase * KDIM + km * 64;
        const __half* wp = Wg + (size_t)nBase * KDIM + km * 64;
        #pragma unroll
        for (int t = 0; t < 4; t++) {
            int f4 = t * 256 + tid;
            int r = f4 >> 3, c = f4 & 7;
            cp_async16(ad + r * (GROWH * 2) + c * 16, ap + (size_t)r * KDIM + c * 8);
            cp_async16(bd + r * (GROWH * 2) + c * 16, wp + (size_t)r * KDIM + c * 8);
        }
        CP_COMMIT();
    };

    load_stage(0);
    load_stage(1);

    for (int km = 0; km < KCH; km++) {
        if (km + 2 <= KCH - 1) cp_wait<1>();
        else                   cp_wait<0>();
        __syncthreads();

        if (km + 2 < KCH) load_stage(km + 2);

        int buf = km % NSTG;
        const __half* Ab = As + buf * STG_H + (wm * 64) * GROWH;
        const __half* Bb = Bs + buf * STG_H + (wn * 32) * GROWH;
        #pragma unroll
        for (int kk = 0; kk < 4; kk++) {
            int kc = kk * 16 + 2 * q;
            uint32_t a[4][4], b[4][2];
            #pragma unroll
            for (int mt = 0; mt < 4; mt++) {
                const __half* p = Ab + (mt * 16 + g) * GROWH + kc;
                a[mt][0] = *(const uint32_t*)&p[0];               // (g,     2q)
                a[mt][1] = *(const uint32_t*)&p[8 * GROWH];       // (g+8,   2q)
                a[mt][2] = *(const uint32_t*)&p[8];               // (g,     2q+8)
                a[mt][3] = *(const uint32_t*)&p[8 * GROWH + 8];   // (g+8,   2q+8)
            }
            #pragma unroll
            for (int nt = 0; nt < 4; nt++) {
                const __half* p = Bb + (nt * 8 + g) * GROWH + kc;
                b[nt][0] = *(const uint32_t*)&p[0];               // (2q,   g)
                b[nt][1] = *(const uint32_t*)&p[8];               // (2q+8, g)
            }
            #pragma unroll
            for (int mt = 0; mt < 4; mt++)
                #pragma unroll
                for (int nt = 0; nt < 4; nt++)
                    mma_f16(d[mt][nt], a[mt], b[nt]);
        }
    }

    #pragma unroll
    for (int mt = 0; mt < 4; mt++) {
        int m0 = mBase + wm * 64 + mt * 16 + g;
        #pragma unroll
        for (int nt = 0; nt < 4; nt++) {
            int n0 = nBase + wn * 32 + nt * 8 + 2 * q;
            float2 bb = *(const float2*)&bias[n0];
            float v0 = d[mt][nt][0] + bb.x;
            float v1 = d[mt][nt][1] + bb.y;
            float v2 = d[mt][nt][2] + bb.x;
            float v3 = d[mt][nt][3] + bb.y;
            if (MODE == 0) {
                scatter_qkv2(m0,     n0, v0, v1);
                scatter_qkv2(m0 + 8, n0, v2, v3);
            } else {
                *(float2*)&C[(size_t)m0 * E_ + n0]       = make_float2(v0, v1);
                *(float2*)&C[(size_t)(m0 + 8) * E_ + n0] = make_float2(v2, v3);
            }
        }
    }
}

// ---------------------------------------------------------------------------
// RoPE on half Q/K: rotate first ROT=32 dims; fp32 math, RN back to half.
// ---------------------------------------------------------------------------
__global__ __launch_bounds__(256) void rope_kernel()
{
    int idx = blockIdx.x * blockDim.x + threadIdx.x;
    if (idx >= B_ * H_ * S_ * (ROT_ / 2)) return;
    int j  = idx & 15;
    int s  = (idx >> 4) & (S_ - 1);
    int bh = idx >> 15;

    float inv = powf(10000.0f, -((float)j) / 16.0f);
    float ang = (float)s * inv;
    float c  = cosf(ang);
    float sn = sinf(ang);

    size_t base = ((size_t)bh * S_ + s) * HS_;
    __half* qp = &g_Qh[base];
    __half* kp = &g_Kh[base];

    float q0 = __half2float(qp[j]), q1 = __half2float(qp[j + 16]);
    qp[j]      = __float2half_rn(q0 * c - q1 * sn);
    qp[j + 16] = __float2half_rn(q1 * c + q0 * sn);

    float k0 = __half2float(kp[j]), k1 = __half2float(kp[j + 16]);
    kp[j]      = __float2half_rn(k0 * c - k1 * sn);
    kp[j + 16] = __float2half_rn(k1 * c + k0 * sn);
}

// ---------------------------------------------------------------------------
// Flash attention fp16: S = Q K^T and O += P V via m16n8k16; fp32 softmax.
// Q/K [rows][d] stride 136 halfs; V^T [d][kv] stride 72; P [q][kv] stride 72.
// S phase: warp w owns q-rows [16w,16w+16). PV: warps 2m x 4n.
// ---------------------------------------------------------------------------
#define FQ 128
#define FKV 64
#define QSTRH 136
#define PSTRH 72
#define VSTRH 72
#define FH_K (FQ * QSTRH)                 // 17408
#define FH_V (FH_K + FKV * QSTRH)         // 26112
#define FH_P (FH_V + HS_ * VSTRH)         // 35328
#define FB_A ((FH_P + FQ * PSTRH) * 2)    // 89088 bytes
#define FB_L (FB_A + FQ * 4)              // 89600
#define FLASH_SMEM (FB_L + FQ * 4)        // 90112 bytes

__global__ __launch_bounds__(256) void flash3_kernel()
{
    extern __shared__ char smc[];
    __half* Qs = (__half*)smc;
    __half* Ks = (__half*)smc + FH_K;
    __half* Vs = (__half*)smc + FH_V;
    __half* Ps = (__half*)smc + FH_P;
    float*  Al = (float*)(smc + FB_A);
    float*  Ll = (float*)(smc + FB_L);
    const uint32_t sQ = smem_to_u32(Qs);
    const uint32_t sK = smem_to_u32(Ks);
    const uint32_t sV = smem_to_u32(Vs);

    const int tid  = threadIdx.x;
    const int wid  = tid >> 5;
    const int lane = tid & 31;
    const int g = lane >> 2, q = lane & 3;
    const int bh = blockIdx.y;
    const int qt = gridDim.x - 1 - blockIdx.x;
    const int qBase = qt * FQ;
    const int wm = wid & 1, wn = wid >> 1;

    const __half* Qg  = g_Qh + ((size_t)bh * S_ + qBase) * HS_;
    const __half* Kg  = g_Kh + (size_t)bh * S_ * HS_;
    const __half* Vtg = g_Vt + (size_t)bh * HS_ * S_;

    // prologue: Q (128 rows x 256B) + K tile 0 (64 rows x 256B)
    #pragma unroll
    for (int i = 0; i < 8; i++) {
        int f4 = i * 256 + tid;
        int r = f4 >> 4, c = f4 & 15;
        cp_async16(sQ + r * (QSTRH * 2) + c * 16, Qg + r * HS_ + c * 8);
    }
    #pragma unroll
    for (int i = 0; i < 4; i++) {
        int f4 = i * 256 + tid;
        int r = f4 >> 4, c = f4 & 15;
        cp_async16(sK + r * (QSTRH * 2) + c * 16, Kg + r * HS_ + c * 8);
    }
    CP_COMMIT();

    float m0 = -1e30f, m1 = -1e30f, l0 = 0.f, l1 = 0.f;
    float o[4][4][4];
    #pragma unroll
    for (int mt = 0; mt < 4; mt++)
        #pragma unroll
        for (int nt = 0; nt < 4; nt++)
            #pragma unroll
            for (int r = 0; r < 4; r++) o[mt][nt][r] = 0.f;

    const int srow0 = wid * 16 + g;
    const int ntiles = 2 * qt + 2;

    for (int t = 0; t < ntiles; t++) {
        cp_wait<0>();
        __syncthreads();

        // prefetch V^T(t): 128 d-rows x 64 kv halfs (128B) — covered by S phase
        #pragma unroll
        for (int i = 0; i < 4; i++) {
            int f4 = i * 256 + tid;
            int r = f4 >> 3, c = f4 & 7;
            cp_async16(sV + r * (VSTRH * 2) + c * 16,
                       Vtg + (size_t)r * S_ + t * FKV + c * 8);
        }
        CP_COMMIT();

        // ---- S = Q K^T (k16 steps over d=128) ----
        float s[8][4];
        #pragma unroll
        for (int nt = 0; nt < 8; nt++)
            #pragma unroll
            for (int r = 0; r < 4; r++) s[nt][r] = 0.f;

        const __half* Aq = Qs + (size_t)(wid * 16 + g) * QSTRH;
        #pragma unroll
        for (int kk = 0; kk < 8; kk++) {
            int kc = kk * 16 + 2 * q;
            uint32_t a[4];
            a[0] = *(const uint32_t*)&Aq[kc];
            a[1] = *(const uint32_t*)&Aq[kc + 8 * QSTRH];
            a[2] = *(const uint32_t*)&Aq[kc + 8];
            a[3] = *(const uint32_t*)&Aq[kc + 8 * QSTRH + 8];
            #pragma unroll
            for (int nt = 0; nt < 8; nt++) {
                const __half* pb = Ks + (size_t)(nt * 8 + g) * QSTRH + kc;
                uint32_t b[2];
                b[0] = *(const uint32_t*)&pb[0];
                b[1] = *(const uint32_t*)&pb[8];
                mma_f16(s[nt], a, b);
            }
        }

        // ---- causal mask (diagonal tiles) ----
        if (t >= 2 * qt) {
            int r0 = qBase + srow0, r1 = r0 + 8;
            #pragma unroll
            for (int nt = 0; nt < 8; nt++) {
                int c0 = t * FKV + nt * 8 + 2 * q;
                if (c0     > r0) s[nt][0] = -1e30f;
                if (c0 + 1 > r0) s[nt][1] = -1e30f;
                if (c0     > r1) s[nt][2] = -1e30f;
                if (c0 + 1 > r1) s[nt][3] = -1e30f;
            }
        }

        // ---- online softmax (rows srow0, srow0+8; quad reduce) ----
        float rm0 = -1e30f, rm1 = -1e30f;
        #pragma unroll
        for (int nt = 0; nt < 8; nt++) {
            rm0 = fmaxf(rm0, fmaxf(s[nt][0], s[nt][1]));
            rm1 = fmaxf(rm1, fmaxf(s[nt][2], s[nt][3]));
        }
        rm0 = fmaxf(rm0, __shfl_xor_sync(0xffffffffu, rm0, 1));
        rm0 = fmaxf(rm0, __shfl_xor_sync(0xffffffffu, rm0, 2));
        rm1 = fmaxf(rm1, __shfl_xor_sync(0xffffffffu, rm1, 1));
        rm1 = fmaxf(rm1, __shfl_xor_sync(0xffffffffu, rm1, 2));
        float mn0 = fmaxf(m0, rm0), mn1 = fmaxf(m1, rm1);
        float al0 = __expf(m0 - mn0), al1 = __expf(m1 - mn1);
        float rs0 = 0.f, rs1 = 0.f;
        #pragma unroll
        for (int nt = 0; nt < 8; nt++) {
            float p0 = __expf(s[nt][0] - mn0);
            float p1 = __expf(s[nt][1] - mn0);
            float p2 = __expf(s[nt][2] - mn1);
            float p3 = __expf(s[nt][3] - mn1);
            rs0 += p0 + p1;
            rs1 += p2 + p3;
            int cl = nt * 8 + 2 * q;
            *(__half2*)&Ps[(size_t)srow0 * PSTRH + cl]       = __floats2half2_rn(p0, p1);
            *(__half2*)&Ps[(size_t)(srow0 + 8) * PSTRH + cl] = __floats2half2_rn(p2, p3);
        }
        rs0 += __shfl_xor_sync(0xffffffffu, rs0, 1);
        rs0 += __shfl_xor_sync(0xffffffffu, rs0, 2);
        rs1 += __shfl_xor_sync(0xffffffffu, rs1, 1);
        rs1 += __shfl_xor_sync(0xffffffffu, rs1, 2);
        l0 = l0 * al0 + rs0;
        l1 = l1 * al1 + rs1;
        m0 = mn0; m1 = mn1;
        if (q == 0) { Al[srow0] = al0; Al[srow0 + 8] = al1; }

        cp_wait<0>();             // V^T(t) arrived
        __syncthreads();          // Ps/Al visible; K buffer free

        // prefetch K(t+1) — covered by PV phase
        if (t + 1 < ntiles) {
            const __half* Kt = Kg + (size_t)(t + 1) * FKV * HS_;
            #pragma unroll
            for (int i = 0; i < 4; i++) {
                int f4 = i * 256 + tid;
                int r = f4 >> 4, c = f4 & 15;
                cp_async16(sK + r * (QSTRH * 2) + c * 16, Kt + r * HS_ + c * 8);
            }
            CP_COMMIT();
        }

        // ---- O rescale + O += P V ----
        #pragma unroll
        for (int mt = 0; mt < 4; mt++) {
            float a0 = Al[wm * 64 + mt * 16 + g];
            float a1 = Al[wm * 64 + mt * 16 + g + 8];
            #pragma unroll
            for (int nt = 0; nt < 4; nt++) {
                o[mt][nt][0] *= a0; o[mt][nt][1] *= a0;
                o[mt][nt][2] *= a1; o[mt][nt][3] *= a1;
            }
        }
        #pragma unroll
        for (int kk = 0; kk < 4; kk++) {
            int kc = kk * 16 + 2 * q;
            uint32_t pa[4][4];
            #pragma unroll
            for (int mt = 0; mt < 4; mt++) {
                const __half* pp = Ps + (size_t)(wm * 64 + mt * 16 + g) * PSTRH + kc;
                pa[mt][0] = *(const uint32_t*)&pp[0];
                pa[mt][1] = *(const uint32_t*)&pp[8 * PSTRH];
                pa[mt][2] = *(const uint32_t*)&pp[8];
                pa[mt][3] = *(const uint32_t*)&pp[8 * PSTRH + 8];
            }
            #pragma unroll
            for (int nt = 0; nt < 4; nt++) {
                const __half* pv = Vs + (size_t)(wn * 32 + nt * 8 + g) * VSTRH + kc;
                uint32_t b[2];
                b[0] = *(const uint32_t*)&pv[0];
                b[1] = *(const uint32_t*)&pv[8];
                #pragma unroll
                for (int mt = 0; mt < 4; mt++)
                    mma_f16(o[mt][nt], pa[mt], b);
            }
        }
    }

    // ---- writeout: normalize, RN to half, store g_Yh [B,S,E] ----
    if (q == 0) { Ll[srow0] = l0; Ll[srow0 + 8] = l1; }
    __syncthreads();
    int b = bh >> 4, h = bh & 15;
    #pragma unroll
    for (int mt = 0; mt < 4; mt++) {
        int r0 = wm * 64 + mt * 16 + g;
        float i0 = 1.f / Ll[r0];
        float i1 = 1.f / Ll[r0 + 8];
        __half* Y0 = g_Yh + ((size_t)b * S_ + qBase + r0) * E_ + h * HS_;
        __half* Y1 = Y0 + 8 * E_;
        #pragma unroll
        for (int nt = 0; nt < 4; nt++) {
            int c0 = wn * 32 + nt * 8 + 2 * q;
            *(__half2*)&Y0[c0] = __floats2half2_rn(o[mt][nt][0] * i0, o[mt][nt][1] * i0);
            *(__half2*)&Y1[c0] = __floats2half2_rn(o[mt][nt][2] * i1, o[mt][nt][3] * i1);
        }
    }
}

// ---------------------------------------------------------------------------
// Launch
// ---------------------------------------------------------------------------
extern "C" void kernel_launch(void* const* d_in, const int* in_sizes, int n_in,
                              void* d_out, int out_size)
{
    const float* x       = (const float*)d_in[0];
    const float* w_qkv   = (const float*)d_in[1];
    const float* b_qkv   = (const float*)d_in[2];
    const float* w_dense = (const float*)d_in[3];
    const float* b_dense = (const float*)d_in[4];
    float* out = (float*)d_out;

    cudaFuncSetAttribute(mma_gemm<0>, cudaFuncAttributeMaxDynamicSharedMemorySize, GEMM_SMEM);
    cudaFuncSetAttribute(mma_gemm<1>, cudaFuncAttributeMaxDynamicSharedMemorySize, GEMM_SMEM);
    cudaFuncSetAttribute(flash3_kernel, cudaFuncAttributeMaxDynamicSharedMemorySize, FLASH_SMEM);

    // 0. Convert GEMM inputs to fp16 (RN)
    convert_kernel<<<(M_ * E_ / 8 + 255) / 256, 256>>>(x, 0, M_ * E_ / 8);
    convert_kernel<<<(NQKV * E_ / 8 + 255) / 256, 256>>>(w_qkv, 1, NQKV * E_ / 8);
    convert_kernel<<<(E_ * E_ / 8 + 255) / 256, 256>>>(w_dense, 2, E_ * E_ / 8);

    // 1. QKV projection + bias -> Qh (scaled) / Kh / V^T (all fp16)
    mma_gemm<0><<<dim3(NQKV / 128, M_ / 128), 256, GEMM_SMEM>>>(b_qkv, nullptr);

    // 2. RoPE on first 32 dims of Q and K
    rope_kernel<<<(B_ * H_ * S_ * (ROT_ / 2)) / 256, 256>>>();

    // 3. Causal flash attention (fp16 mma) -> g_Yh
    flash3_kernel<<<dim3(S_ / FQ, B_ * H_), 256, FLASH_SMEM>>>();

    // 4. Dense projection + bias -> fp32 output
    mma_gemm<1><<<dim3(E_ / 128, M_ / 128), 256, GEMM_SMEM>>>(b_dense, out);
}